// round 1
// baseline (speedup 1.0000x reference)
#include <cuda_runtime.h>
#include <math.h>

// ---------------- problem constants ----------------
#define BB    32
#define NTOK  196
#define NP1   197
#define TKN   768
#define HH    12
#define ZZ    64
#define HIDN  3072
#define MROWS (BB*NP1)    // 6304
#define MENC  (BB*NTOK)   // 6272
#define BHN   (BB*HH)     // 384
#define KSTEPS 12
#define BETA_S 0.125f
#define EPS_LN 1e-5f

// ---------------- scratch (device globals; no allocation) ----------------
__device__ float g_t [MROWS*TKN];
__device__ float g_g [MROWS*TKN];
__device__ float g_q [MROWS*TKN];
__device__ float g_k [MROWS*TKN];
__device__ float g_dq[MROWS*TKN];
__device__ float g_dk[MROWS*TKN];
__device__ float g_h [MROWS*HIDN];
__device__ float g_P [BHN*NP1*NP1];

// ---------------- GEMM: C = A[M,K] * B[N,K]^T (+bias)(+relu) ----------------
// BM=BN=128, BK=16, 256 threads, 8x8 microtile.
template<bool BIAS, bool RELU>
__global__ void __launch_bounds__(256) gemm_nt_k(
    const float* __restrict__ A, const float* __restrict__ B,
    const float* __restrict__ bias, float* __restrict__ C,
    int M, int N, int K)
{
    __shared__ float As[16][132];
    __shared__ float Bs[16][132];
    const int tid = threadIdx.x;
    const int m0 = blockIdx.y * 128;
    const int n0 = blockIdx.x * 128;
    const int tx = tid & 15;
    const int ty = tid >> 4;
    float acc[8][8];
#pragma unroll
    for (int i = 0; i < 8; i++)
#pragma unroll
        for (int j = 0; j < 8; j++) acc[i][j] = 0.f;

    for (int kt = 0; kt < K; kt += 16) {
#pragma unroll
        for (int s = 0; s < 2; s++) {
            int f4  = tid + s * 256;
            int row = f4 >> 2;
            int kc  = (f4 & 3) << 2;
            float4 av = make_float4(0.f, 0.f, 0.f, 0.f);
            int gm = m0 + row;
            if (gm < M) av = *(const float4*)(A + (size_t)gm * K + kt + kc);
            As[kc + 0][row] = av.x; As[kc + 1][row] = av.y;
            As[kc + 2][row] = av.z; As[kc + 3][row] = av.w;
            float4 bv = *(const float4*)(B + (size_t)(n0 + row) * K + kt + kc);
            Bs[kc + 0][row] = bv.x; Bs[kc + 1][row] = bv.y;
            Bs[kc + 2][row] = bv.z; Bs[kc + 3][row] = bv.w;
        }
        __syncthreads();
#pragma unroll
        for (int kk = 0; kk < 16; kk++) {
            float a[8], b[8];
            *(float4*)&a[0] = *(const float4*)&As[kk][ty * 8];
            *(float4*)&a[4] = *(const float4*)&As[kk][ty * 8 + 4];
            *(float4*)&b[0] = *(const float4*)&Bs[kk][tx * 8];
            *(float4*)&b[4] = *(const float4*)&Bs[kk][tx * 8 + 4];
#pragma unroll
            for (int i = 0; i < 8; i++)
#pragma unroll
                for (int j = 0; j < 8; j++) acc[i][j] += a[i] * b[j];
        }
        __syncthreads();
    }
#pragma unroll
    for (int i = 0; i < 8; i++) {
        int gm = m0 + ty * 8 + i;
        if (gm < M) {
            float* crow = C + (size_t)gm * N + n0 + tx * 8;
#pragma unroll
            for (int j = 0; j < 8; j++) {
                float v = acc[i][j];
                if (BIAS) v += bias[n0 + tx * 8 + j];
                if (RELU) v = fmaxf(v, 0.f);
                crow[j] = v;
            }
        }
    }
}

// ---------------- GEMM: C += A[M,K] * B[K,N]  (accumulating NN) ----------------
__global__ void __launch_bounds__(256) gemm_nn_acc_k(
    const float* __restrict__ A, const float* __restrict__ B,
    float* __restrict__ C, int M, int N, int K)
{
    __shared__ float As[16][132];
    __shared__ float Bs[16][132];
    const int tid = threadIdx.x;
    const int m0 = blockIdx.y * 128;
    const int n0 = blockIdx.x * 128;
    const int tx = tid & 15;
    const int ty = tid >> 4;
    float acc[8][8];
#pragma unroll
    for (int i = 0; i < 8; i++)
#pragma unroll
        for (int j = 0; j < 8; j++) acc[i][j] = 0.f;

    for (int kt = 0; kt < K; kt += 16) {
#pragma unroll
        for (int s = 0; s < 2; s++) {
            int f4  = tid + s * 256;
            int row = f4 >> 2;
            int kc  = (f4 & 3) << 2;
            float4 av = make_float4(0.f, 0.f, 0.f, 0.f);
            int gm = m0 + row;
            if (gm < M) av = *(const float4*)(A + (size_t)gm * K + kt + kc);
            As[kc + 0][row] = av.x; As[kc + 1][row] = av.y;
            As[kc + 2][row] = av.z; As[kc + 3][row] = av.w;

            int krow = f4 >> 5;
            int nc   = (f4 & 31) << 2;
            float4 bv = *(const float4*)(B + (size_t)(kt + krow) * N + n0 + nc);
            *(float4*)&Bs[krow][nc] = bv;
        }
        __syncthreads();
#pragma unroll
        for (int kk = 0; kk < 16; kk++) {
            float a[8], b[8];
            *(float4*)&a[0] = *(const float4*)&As[kk][ty * 8];
            *(float4*)&a[4] = *(const float4*)&As[kk][ty * 8 + 4];
            *(float4*)&b[0] = *(const float4*)&Bs[kk][tx * 8];
            *(float4*)&b[4] = *(const float4*)&Bs[kk][tx * 8 + 4];
#pragma unroll
            for (int i = 0; i < 8; i++)
#pragma unroll
                for (int j = 0; j < 8; j++) acc[i][j] += a[i] * b[j];
        }
        __syncthreads();
    }
#pragma unroll
    for (int i = 0; i < 8; i++) {
        int gm = m0 + ty * 8 + i;
        if (gm < M) {
            float* crow = C + (size_t)gm * N + n0 + tx * 8;
#pragma unroll
            for (int j = 0; j < 8; j++) crow[j] += acc[i][j];
        }
    }
}

// ---------------- LayerNorm (scalar or vector gain) ----------------
__device__ __forceinline__ float block_sum_256(float v, float* red)
{
    int lane = threadIdx.x & 31, w = threadIdx.x >> 5;
#pragma unroll
    for (int o = 16; o; o >>= 1) v += __shfl_xor_sync(0xffffffffu, v, o);
    if (lane == 0) red[w] = v;
    __syncthreads();
    if (w == 0) {
        float r = (lane < 8) ? red[lane] : 0.f;
#pragma unroll
        for (int o = 4; o; o >>= 1) r += __shfl_xor_sync(0xffffffffu, r, o);
        if (lane == 0) red[0] = r;
    }
    __syncthreads();
    float out = red[0];
    __syncthreads();
    return out;
}

__global__ void __launch_bounds__(256) ln_kernel(
    const float* __restrict__ X, const float* __restrict__ w,
    const float* __restrict__ bvec, float* __restrict__ Y, int scalar_w)
{
    __shared__ float red[32];
    int row = blockIdx.x;
    const float* x = X + (size_t)row * TKN;
    float* y = Y + (size_t)row * TKN;
    int tid = threadIdx.x;
    float v[3];
    float s = 0.f, ss = 0.f;
#pragma unroll
    for (int i = 0; i < 3; i++) {
        float t = x[tid + i * 256];
        v[i] = t; s += t; ss += t * t;
    }
    float sum  = block_sum_256(s, red);
    float sum2 = block_sum_256(ss, red);
    float mu = sum * (1.f / TKN);
    float var = sum2 * (1.f / TKN) - mu * mu;
    float r = rsqrtf(var + EPS_LN);
#pragma unroll
    for (int i = 0; i < 3; i++) {
        int c = tid + i * 256;
        float g = (v[i] - mu) * r;
        float wv = scalar_w ? w[0] : w[c];
        y[c] = g * wv + bvec[c];
    }
}

// ---------------- assemble t = [cls ; enc] + pos ----------------
__global__ void assemble_t_k(const float* __restrict__ enc,
                             const float* __restrict__ cls,
                             const float* __restrict__ pos)
{
    int idx = blockIdx.x * 256 + threadIdx.x;
    if (idx >= MROWS * TKN) return;
    int d = idx % TKN;
    int row = idx / TKN;
    int b = row / NP1, n = row % NP1;
    float v;
    if (n == 0) v = cls[d];
    else        v = enc[((size_t)(b * NTOK + n - 1)) * TKN + d];
    g_t[idx] = v + pos[n * TKN + d];
}

// ---------------- attention scores: P = beta * Qh Kh^T (batched over b,h) ----------------
__global__ void __launch_bounds__(256) attn_scores_k(
    const float* __restrict__ Q, const float* __restrict__ Kv, float* __restrict__ P)
{
    int bh = blockIdx.z;
    int b = bh / HH, h = bh % HH;
    const float* Qh = Q  + (size_t)b * NP1 * TKN + h * ZZ;
    const float* Kh = Kv + (size_t)b * NP1 * TKN + h * ZZ;
    int q0 = blockIdx.y * 32, k0 = blockIdx.x * 32;
    __shared__ float Qs[32][68];
    __shared__ float Kst[64][33];
    int tid = threadIdx.x;
#pragma unroll
    for (int s = 0; s < 2; s++) {
        int f4 = tid + s * 256;
        int r = f4 >> 4;
        int c4 = (f4 & 15) << 2;
        int gq = q0 + r;
        float4 qv = (gq < NP1) ? *(const float4*)(Qh + (size_t)gq * TKN + c4)
                               : make_float4(0.f, 0.f, 0.f, 0.f);
        *(float4*)&Qs[r][c4] = qv;
        int gk = k0 + r;
        float4 kv = (gk < NP1) ? *(const float4*)(Kh + (size_t)gk * TKN + c4)
                               : make_float4(0.f, 0.f, 0.f, 0.f);
        Kst[c4 + 0][r] = kv.x; Kst[c4 + 1][r] = kv.y;
        Kst[c4 + 2][r] = kv.z; Kst[c4 + 3][r] = kv.w;
    }
    __syncthreads();
    int tx = tid & 15, ty = tid >> 4;
    int r0 = ty * 2, r1 = r0 + 1, c0 = tx * 2, c1 = c0 + 1;
    float a00 = 0.f, a01 = 0.f, a10 = 0.f, a11 = 0.f;
#pragma unroll
    for (int z = 0; z < ZZ; z++) {
        float qa = Qs[r0][z], qb = Qs[r1][z];
        float ka = Kst[z][c0], kb = Kst[z][c1];
        a00 += qa * ka; a01 += qa * kb; a10 += qb * ka; a11 += qb * kb;
    }
    float* Pp = P + (size_t)bh * NP1 * NP1;
    int gq0 = q0 + r0, gq1 = q0 + r1, gk0 = k0 + c0, gk1 = k0 + c1;
    if (gq0 < NP1) {
        if (gk0 < NP1) Pp[(size_t)gq0 * NP1 + gk0] = BETA_S * a00;
        if (gk1 < NP1) Pp[(size_t)gq0 * NP1 + gk1] = BETA_S * a01;
    }
    if (gq1 < NP1) {
        if (gk0 < NP1) Pp[(size_t)gq1 * NP1 + gk0] = BETA_S * a10;
        if (gk1 < NP1) Pp[(size_t)gq1 * NP1 + gk1] = BETA_S * a11;
    }
}

// ---------------- row softmax over P (rows of length 197) ----------------
__global__ void __launch_bounds__(256) softmax_rows_k(float* __restrict__ P)
{
    int row = blockIdx.x * 8 + (threadIdx.x >> 5);
    if (row >= BHN * NP1) return;
    int lane = threadIdx.x & 31;
    float* p = P + (size_t)row * NP1;
    float vals[7];
    float m = -1e30f;
#pragma unroll
    for (int i = 0; i < 7; i++) {
        int c = lane + i * 32;
        float v = (c < NP1) ? p[c] : -1e30f;
        vals[i] = v;
        m = fmaxf(m, v);
    }
#pragma unroll
    for (int o = 16; o; o >>= 1) m = fmaxf(m, __shfl_xor_sync(0xffffffffu, m, o));
    float s = 0.f;
#pragma unroll
    for (int i = 0; i < 7; i++) {
        int c = lane + i * 32;
        float e = (c < NP1) ? expf(vals[i] - m) : 0.f;
        vals[i] = e; s += e;
    }
#pragma unroll
    for (int o = 16; o; o >>= 1) s += __shfl_xor_sync(0xffffffffu, s, o);
    float inv = 1.f / s;
#pragma unroll
    for (int i = 0; i < 7; i++) {
        int c = lane + i * 32;
        if (c < NP1) p[c] = vals[i] * inv;
    }
}

// ---------------- batched PV: Out[n,z] = sum_k op(P)[n,k] * V[k,z] ----------------
// TRANSP=false: dq = P @ Kh ; TRANSP=true: dk = P^T @ Qh
template<bool TRANSP>
__global__ void __launch_bounds__(256) attn_av_k(
    const float* __restrict__ P, const float* __restrict__ V, float* __restrict__ Out)
{
    int bh = blockIdx.y;
    int b = bh / HH, h = bh % HH;
    const float* Pp = P + (size_t)bh * NP1 * NP1;
    const float* Vh = V   + (size_t)b * NP1 * TKN + h * ZZ;
    float*       Oh = Out + (size_t)b * NP1 * TKN + h * ZZ;
    int n0 = blockIdx.x * 32;
    __shared__ float Ps[32][33];
    __shared__ float Vs[32][64];
    int tid = threadIdx.x;
    int tx = tid & 63, ty = tid >> 6;
    float acc[8];
#pragma unroll
    for (int i = 0; i < 8; i++) acc[i] = 0.f;

    for (int kb = 0; kb < NP1; kb += 32) {
#pragma unroll
        for (int s = 0; s < 4; s++) {
            int idx = tid + s * 256;
            int r = idx >> 5, kk = idx & 31;
            float v = 0.f;
            int n = n0 + r, k = kb + kk;
            if (n < NP1 && k < NP1)
                v = TRANSP ? Pp[(size_t)k * NP1 + n] : Pp[(size_t)n * NP1 + k];
            Ps[r][kk] = v;
        }
#pragma unroll
        for (int s = 0; s < 2; s++) {
            int f4 = tid + s * 256;
            int r = f4 >> 4, c4 = (f4 & 15) << 2;
            int k = kb + r;
            float4 v = (k < NP1) ? *(const float4*)(Vh + (size_t)k * TKN + c4)
                                 : make_float4(0.f, 0.f, 0.f, 0.f);
            *(float4*)&Vs[r][c4] = v;
        }
        __syncthreads();
#pragma unroll
        for (int kk = 0; kk < 32; kk++) {
            float bv = Vs[kk][tx];
#pragma unroll
            for (int i = 0; i < 8; i++) acc[i] += Ps[ty + 4 * i][kk] * bv;
        }
        __syncthreads();
    }
#pragma unroll
    for (int i = 0; i < 8; i++) {
        int n = n0 + ty + 4 * i;
        if (n < NP1) Oh[(size_t)n * TKN + tx] = acc[i];
    }
}

// ---------------- final copy (drop cls row) ----------------
__global__ void copy_out_k(const float* __restrict__ Y, float* __restrict__ out)
{
    int idx = blockIdx.x * 256 + threadIdx.x;
    if (idx >= BB * NTOK * TKN) return;
    int d = idx % TKN;
    int r = idx / TKN;
    int b = r / NTOK, j = r % NTOK;
    out[idx] = Y[((size_t)(b * NP1 + j + 1)) * TKN + d];
}

// ---------------- driver ----------------
extern "C" void kernel_launch(void* const* d_in, const int* in_sizes, int n_in,
                              void* d_out, int out_size)
{
    const float* x      = (const float*)d_in[0];
    const float* w_enc  = (const float*)d_in[1];
    const float* b_enc  = (const float*)d_in[2];
    const float* cls    = (const float*)d_in[3];
    const float* pos    = (const float*)d_in[4];
    const float* eln_g  = (const float*)d_in[5];
    const float* eln_b  = (const float*)d_in[6];
    const float* wq     = (const float*)d_in[7];
    const float* wk     = (const float*)d_in[8];
    const float* w_hop  = (const float*)d_in[9];
    const float* dec_w  = (const float*)d_in[10];
    const float* dec_b  = (const float*)d_in[11];
    const float* w_dec  = (const float*)d_in[12];
    const float* b_dec  = (const float*)d_in[13];
    float* out = (float*)d_out;

    float *t_, *g_, *q_, *k_, *dq_, *dk_, *h_, *P_;
    cudaGetSymbolAddress((void**)&t_,  g_t);
    cudaGetSymbolAddress((void**)&g_,  g_g);
    cudaGetSymbolAddress((void**)&q_,  g_q);
    cudaGetSymbolAddress((void**)&k_,  g_k);
    cudaGetSymbolAddress((void**)&dq_, g_dq);
    cudaGetSymbolAddress((void**)&dk_, g_dk);
    cudaGetSymbolAddress((void**)&h_,  g_h);
    cudaGetSymbolAddress((void**)&P_,  g_P);

    const dim3 blk(256);
    const dim3 grid768(TKN / 128, (MROWS + 127) / 128);      // (6, 50)
    const dim3 gridHid(HIDN / 128, (MROWS + 127) / 128);     // (24, 50)
    const dim3 gridEnc(TKN / 128, (MENC + 127) / 128);       // (6, 49)

    // encode: enc = x @ w_enc^T + b_enc   (temp in q_)
    gemm_nt_k<true, false><<<gridEnc, blk>>>(x, w_enc, b_enc, q_, MENC, TKN, TKN);
    assemble_t_k<<<(MROWS * TKN + 255) / 256, blk>>>(q_, cls, pos);

    for (int s = 0; s < KSTEPS; s++) {
        ln_kernel<<<MROWS, blk>>>(t_, eln_g, eln_b, g_, 1);
        gemm_nt_k<false, false><<<grid768, blk>>>(g_, wq, nullptr, q_, MROWS, TKN, TKN);
        gemm_nt_k<false, false><<<grid768, blk>>>(g_, wk, nullptr, k_, MROWS, TKN, TKN);
        attn_scores_k<<<dim3(7, 7, BHN), blk>>>(q_, k_, P_);
        softmax_rows_k<<<(BHN * NP1 + 7) / 8, blk>>>(P_);
        attn_av_k<false><<<dim3(7, BHN), blk>>>(P_, k_, dq_);
        attn_av_k<true ><<<dim3(7, BHN), blk>>>(P_, q_, dk_);
        gemm_nt_k<false, true><<<gridHid, blk>>>(g_, w_hop, nullptr, h_, MROWS, HIDN, TKN);
        gemm_nn_acc_k<<<grid768, blk>>>(dq_, wq, t_, MROWS, TKN, TKN);
        gemm_nn_acc_k<<<grid768, blk>>>(dk_, wk, t_, MROWS, TKN, TKN);
        gemm_nn_acc_k<<<grid768, blk>>>(h_, w_hop, t_, MROWS, TKN, HIDN);
    }

    ln_kernel<<<MROWS, blk>>>(t_, dec_w, dec_b, g_, 0);
    gemm_nt_k<true, false><<<grid768, blk>>>(g_, w_dec, b_dec, q_, MROWS, TKN, TKN);
    copy_out_k<<<(BB * NTOK * TKN + 255) / 256, blk>>>(q_, out);
}

// round 2
// speedup vs baseline: 1.5368x; 1.5368x over previous
#include <cuda_runtime.h>
#include <math.h>

// ---------------- problem constants ----------------
#define BB    32
#define NTOK  196
#define NP1   197
#define TKN   768
#define HH    12
#define ZZ    64
#define HIDN  3072
#define MROWS (BB*NP1)    // 6304
#define MENC  (BB*NTOK)   // 6272
#define BHN   (BB*HH)     // 384
#define KSTEPS 12
#define BETA_S 0.125f
#define EPS_LN 1e-5f

// ---------------- scratch (device globals; no allocation) ----------------
__device__ float g_t [MROWS*TKN];
__device__ float g_g [MROWS*TKN];
__device__ float g_q [MROWS*TKN];
__device__ float g_k [MROWS*TKN];
__device__ float g_dq[MROWS*TKN];
__device__ float g_dk[MROWS*TKN];
__device__ float g_h [MROWS*HIDN];
__device__ float g_P [BHN*NP1*NP1];

// ================== tf32 tensor-core GEMM ==================
// C[M,N] (fp32) = A[M,K] * op(B)   (+bias)(+relu)(+accumulate)
// NN=false: B is [N,K] row-major (C = A * B^T)
// NN=true : B is [K,N] row-major (C = A * B)
// BM=BN=128, BK=32, 256 threads (8 warps, 2x4), warp tile 64x32.

#define A_STRIDE 36
#define BT_STRIDE 36
#define BN_STRIDE 136
#define A_ELEMS  (128*A_STRIDE)   // 4608
#define SMEM_GEMM_BYTES ((2*A_ELEMS + 2*A_ELEMS) * 4)  // 73728

__device__ __forceinline__ unsigned f2tf(float f) {
    unsigned u;
    asm("cvt.rna.tf32.f32 %0, %1;" : "=r"(u) : "f"(f));
    return u;
}

__device__ __forceinline__ void mma8(float c[4], const unsigned a[4], const unsigned b[2]) {
    asm volatile(
        "mma.sync.aligned.m16n8k8.row.col.f32.tf32.tf32.f32 "
        "{%0,%1,%2,%3}, {%4,%5,%6,%7}, {%8,%9}, {%0,%1,%2,%3};\n"
        : "+f"(c[0]), "+f"(c[1]), "+f"(c[2]), "+f"(c[3])
        : "r"(a[0]), "r"(a[1]), "r"(a[2]), "r"(a[3]), "r"(b[0]), "r"(b[1]));
}

template<bool NN>
__device__ __forceinline__ void ldg_tiles(
    const float* __restrict__ A, const float* __restrict__ B,
    int M, int N, int K, int m0, int n0, int kt, int tid,
    float4 aR[4], float4 bR[4])
{
#pragma unroll
    for (int s = 0; s < 4; s++) {
        int id = tid + s * 256;
        int r = id >> 3, c = (id & 7) << 2;
        int gm = m0 + r;
        aR[s] = (gm < M) ? *(const float4*)(A + (size_t)gm * K + kt + c)
                         : make_float4(0.f, 0.f, 0.f, 0.f);
        if (!NN) {
            bR[s] = *(const float4*)(B + (size_t)(n0 + r) * K + kt + c);
        } else {
            int rb = id >> 5, cb = (id & 31) << 2;
            bR[s] = *(const float4*)(B + (size_t)(kt + rb) * N + n0 + cb);
        }
    }
}

template<bool NN>
__device__ __forceinline__ void sts_tiles(
    unsigned* Ab, unsigned* Bb, int tid,
    const float4 aR[4], const float4 bR[4])
{
#pragma unroll
    for (int s = 0; s < 4; s++) {
        int id = tid + s * 256;
        int r = id >> 3, c = (id & 7) << 2;
        uint4 ua = make_uint4(f2tf(aR[s].x), f2tf(aR[s].y), f2tf(aR[s].z), f2tf(aR[s].w));
        *(uint4*)(Ab + r * A_STRIDE + c) = ua;
        uint4 ub = make_uint4(f2tf(bR[s].x), f2tf(bR[s].y), f2tf(bR[s].z), f2tf(bR[s].w));
        if (!NN) {
            *(uint4*)(Bb + r * BT_STRIDE + c) = ub;
        } else {
            int rb = id >> 5, cb = (id & 31) << 2;
            *(uint4*)(Bb + rb * BN_STRIDE + cb) = ub;
        }
    }
}

template<bool NN, bool BIAS, bool RELU, bool ACC>
__global__ void __launch_bounds__(256, 1) mma_gemm_k(
    const float* __restrict__ A, const float* __restrict__ B,
    const float* __restrict__ bias, float* __restrict__ C,
    int M, int N, int K)
{
    extern __shared__ unsigned sm[];
    unsigned* Asb[2] = { sm,            sm + A_ELEMS };
    unsigned* Bsb[2] = { sm + 2*A_ELEMS, sm + 3*A_ELEMS };

    const int tid = threadIdx.x;
    const int m0 = blockIdx.y * 128, n0 = blockIdx.x * 128;
    const int lane = tid & 31, wid = tid >> 5;
    const int wm = (wid & 1) * 64, wn = (wid >> 1) * 32;
    const int g = lane >> 2, tig = lane & 3;

    float acc[4][4][4];
#pragma unroll
    for (int mi = 0; mi < 4; mi++)
#pragma unroll
        for (int ni = 0; ni < 4; ni++)
#pragma unroll
            for (int v = 0; v < 4; v++) acc[mi][ni][v] = 0.f;

    float4 aR[4], bR[4];
    ldg_tiles<NN>(A, B, M, N, K, m0, n0, 0, tid, aR, bR);
    sts_tiles<NN>(Asb[0], Bsb[0], tid, aR, bR);
    __syncthreads();

    const int niter = K >> 5;
    int cur = 0;
    for (int it = 0; it < niter; it++) {
        if (it + 1 < niter)
            ldg_tiles<NN>(A, B, M, N, K, m0, n0, (it + 1) << 5, tid, aR, bR);

        const unsigned* Ab = Asb[cur];
        const unsigned* Bb = Bsb[cur];
#pragma unroll
        for (int ks = 0; ks < 4; ks++) {
            unsigned af[4][4], bf[4][2];
#pragma unroll
            for (int mi = 0; mi < 4; mi++) {
                const unsigned* p0 = Ab + (wm + mi * 16 + g) * A_STRIDE + ks * 8 + tig;
                af[mi][0] = p0[0];
                af[mi][2] = p0[4];
                const unsigned* p1 = p0 + 8 * A_STRIDE;
                af[mi][1] = p1[0];
                af[mi][3] = p1[4];
            }
#pragma unroll
            for (int ni = 0; ni < 4; ni++) {
                if (!NN) {
                    const unsigned* p = Bb + (wn + ni * 8 + g) * BT_STRIDE + ks * 8 + tig;
                    bf[ni][0] = p[0];
                    bf[ni][1] = p[4];
                } else {
                    const unsigned* p = Bb + (ks * 8 + tig) * BN_STRIDE + wn + ni * 8 + g;
                    bf[ni][0] = p[0];
                    bf[ni][1] = p[4 * BN_STRIDE];
                }
            }
#pragma unroll
            for (int mi = 0; mi < 4; mi++)
#pragma unroll
                for (int ni = 0; ni < 4; ni++)
                    mma8(acc[mi][ni], af[mi], bf[ni]);
        }

        if (it + 1 < niter) {
            sts_tiles<NN>(Asb[cur ^ 1], Bsb[cur ^ 1], tid, aR, bR);
            __syncthreads();
            cur ^= 1;
        }
    }

    // epilogue
#pragma unroll
    for (int mi = 0; mi < 4; mi++) {
        int r0 = m0 + wm + mi * 16 + g;
#pragma unroll
        for (int half = 0; half < 2; half++) {
            int row = r0 + half * 8;
            if (row < M) {
                float* crow = C + (size_t)row * N;
#pragma unroll
                for (int ni = 0; ni < 4; ni++) {
                    int col = n0 + wn + ni * 8 + tig * 2;
                    float v0 = acc[mi][ni][half * 2 + 0];
                    float v1 = acc[mi][ni][half * 2 + 1];
                    if (BIAS) { v0 += bias[col]; v1 += bias[col + 1]; }
                    if (RELU) { v0 = fmaxf(v0, 0.f); v1 = fmaxf(v1, 0.f); }
                    if (ACC)  { v0 += crow[col]; v1 += crow[col + 1]; }
                    crow[col] = v0;
                    crow[col + 1] = v1;
                }
            }
        }
    }
}

// ---------------- LayerNorm (scalar or vector gain) ----------------
__device__ __forceinline__ float block_sum_256(float v, float* red)
{
    int lane = threadIdx.x & 31, w = threadIdx.x >> 5;
#pragma unroll
    for (int o = 16; o; o >>= 1) v += __shfl_xor_sync(0xffffffffu, v, o);
    if (lane == 0) red[w] = v;
    __syncthreads();
    if (w == 0) {
        float r = (lane < 8) ? red[lane] : 0.f;
#pragma unroll
        for (int o = 4; o; o >>= 1) r += __shfl_xor_sync(0xffffffffu, r, o);
        if (lane == 0) red[0] = r;
    }
    __syncthreads();
    float out = red[0];
    __syncthreads();
    return out;
}

__global__ void __launch_bounds__(256) ln_kernel(
    const float* __restrict__ X, const float* __restrict__ w,
    const float* __restrict__ bvec, float* __restrict__ Y, int scalar_w)
{
    __shared__ float red[32];
    int row = blockIdx.x;
    const float* x = X + (size_t)row * TKN;
    float* y = Y + (size_t)row * TKN;
    int tid = threadIdx.x;
    float v[3];
    float s = 0.f, ss = 0.f;
#pragma unroll
    for (int i = 0; i < 3; i++) {
        float t = x[tid + i * 256];
        v[i] = t; s += t; ss += t * t;
    }
    float sum  = block_sum_256(s, red);
    float sum2 = block_sum_256(ss, red);
    float mu = sum * (1.f / TKN);
    float var = sum2 * (1.f / TKN) - mu * mu;
    float r = rsqrtf(var + EPS_LN);
#pragma unroll
    for (int i = 0; i < 3; i++) {
        int c = tid + i * 256;
        float gv = (v[i] - mu) * r;
        float wv = scalar_w ? w[0] : w[c];
        y[c] = gv * wv + bvec[c];
    }
}

// ---------------- assemble t = [cls ; enc] + pos ----------------
__global__ void assemble_t_k(const float* __restrict__ enc,
                             const float* __restrict__ cls,
                             const float* __restrict__ pos)
{
    int idx = blockIdx.x * 256 + threadIdx.x;
    if (idx >= MROWS * TKN) return;
    int d = idx % TKN;
    int row = idx / TKN;
    int b = row / NP1, n = row % NP1;
    float v;
    if (n == 0) v = cls[d];
    else        v = enc[((size_t)(b * NTOK + n - 1)) * TKN + d];
    g_t[idx] = v + pos[n * TKN + d];
}

// ---------------- attention scores: P = beta * Qh Kh^T (batched over b,h) ----------------
__global__ void __launch_bounds__(256) attn_scores_k(
    const float* __restrict__ Q, const float* __restrict__ Kv, float* __restrict__ P)
{
    int bh = blockIdx.z;
    int b = bh / HH, h = bh % HH;
    const float* Qh = Q  + (size_t)b * NP1 * TKN + h * ZZ;
    const float* Kh = Kv + (size_t)b * NP1 * TKN + h * ZZ;
    int q0 = blockIdx.y * 32, k0 = blockIdx.x * 32;
    __shared__ float Qs[32][68];
    __shared__ float Kst[64][33];
    int tid = threadIdx.x;
#pragma unroll
    for (int s = 0; s < 2; s++) {
        int f4 = tid + s * 256;
        int r = f4 >> 4;
        int c4 = (f4 & 15) << 2;
        int gq = q0 + r;
        float4 qv = (gq < NP1) ? *(const float4*)(Qh + (size_t)gq * TKN + c4)
                               : make_float4(0.f, 0.f, 0.f, 0.f);
        *(float4*)&Qs[r][c4] = qv;
        int gk = k0 + r;
        float4 kv = (gk < NP1) ? *(const float4*)(Kh + (size_t)gk * TKN + c4)
                               : make_float4(0.f, 0.f, 0.f, 0.f);
        Kst[c4 + 0][r] = kv.x; Kst[c4 + 1][r] = kv.y;
        Kst[c4 + 2][r] = kv.z; Kst[c4 + 3][r] = kv.w;
    }
    __syncthreads();
    int tx = tid & 15, ty = tid >> 4;
    int r0 = ty * 2, r1 = r0 + 1, c0 = tx * 2, c1 = c0 + 1;
    float a00 = 0.f, a01 = 0.f, a10 = 0.f, a11 = 0.f;
#pragma unroll
    for (int z = 0; z < ZZ; z++) {
        float qa = Qs[r0][z], qb = Qs[r1][z];
        float ka = Kst[z][c0], kb = Kst[z][c1];
        a00 += qa * ka; a01 += qa * kb; a10 += qb * ka; a11 += qb * kb;
    }
    float* Pp = P + (size_t)bh * NP1 * NP1;
    int gq0 = q0 + r0, gq1 = q0 + r1, gk0 = k0 + c0, gk1 = k0 + c1;
    if (gq0 < NP1) {
        if (gk0 < NP1) Pp[(size_t)gq0 * NP1 + gk0] = BETA_S * a00;
        if (gk1 < NP1) Pp[(size_t)gq0 * NP1 + gk1] = BETA_S * a01;
    }
    if (gq1 < NP1) {
        if (gk0 < NP1) Pp[(size_t)gq1 * NP1 + gk0] = BETA_S * a10;
        if (gk1 < NP1) Pp[(size_t)gq1 * NP1 + gk1] = BETA_S * a11;
    }
}

// ---------------- row softmax over P (rows of length 197) ----------------
__global__ void __launch_bounds__(256) softmax_rows_k(float* __restrict__ P)
{
    int row = blockIdx.x * 8 + (threadIdx.x >> 5);
    if (row >= BHN * NP1) return;
    int lane = threadIdx.x & 31;
    float* p = P + (size_t)row * NP1;
    float vals[7];
    float m = -1e30f;
#pragma unroll
    for (int i = 0; i < 7; i++) {
        int c = lane + i * 32;
        float v = (c < NP1) ? p[c] : -1e30f;
        vals[i] = v;
        m = fmaxf(m, v);
    }
#pragma unroll
    for (int o = 16; o; o >>= 1) m = fmaxf(m, __shfl_xor_sync(0xffffffffu, m, o));
    float s = 0.f;
#pragma unroll
    for (int i = 0; i < 7; i++) {
        int c = lane + i * 32;
        float e = (c < NP1) ? expf(vals[i] - m) : 0.f;
        vals[i] = e; s += e;
    }
#pragma unroll
    for (int o = 16; o; o >>= 1) s += __shfl_xor_sync(0xffffffffu, s, o);
    float inv = 1.f / s;
#pragma unroll
    for (int i = 0; i < 7; i++) {
        int c = lane + i * 32;
        if (c < NP1) p[c] = vals[i] * inv;
    }
}

// ---------------- batched PV: Out[n,z] = sum_k op(P)[n,k] * V[k,z] ----------------
template<bool TRANSP>
__global__ void __launch_bounds__(256) attn_av_k(
    const float* __restrict__ P, const float* __restrict__ V, float* __restrict__ Out)
{
    int bh = blockIdx.y;
    int b = bh / HH, h = bh % HH;
    const float* Pp = P + (size_t)bh * NP1 * NP1;
    const float* Vh = V   + (size_t)b * NP1 * TKN + h * ZZ;
    float*       Oh = Out + (size_t)b * NP1 * TKN + h * ZZ;
    int n0 = blockIdx.x * 32;
    __shared__ float Ps[32][33];
    __shared__ float Vs[32][64];
    int tid = threadIdx.x;
    int tx = tid & 63, ty = tid >> 6;
    float acc[8];
#pragma unroll
    for (int i = 0; i < 8; i++) acc[i] = 0.f;

    for (int kb = 0; kb < NP1; kb += 32) {
#pragma unroll
        for (int s = 0; s < 4; s++) {
            int idx = tid + s * 256;
            int r = idx >> 5, kk = idx & 31;
            float v = 0.f;
            int n = n0 + r, k = kb + kk;
            if (n < NP1 && k < NP1)
                v = TRANSP ? Pp[(size_t)k * NP1 + n] : Pp[(size_t)n * NP1 + k];
            Ps[r][kk] = v;
        }
#pragma unroll
        for (int s = 0; s < 2; s++) {
            int f4 = tid + s * 256;
            int r = f4 >> 4, c4 = (f4 & 15) << 2;
            int k = kb + r;
            float4 v = (k < NP1) ? *(const float4*)(Vh + (size_t)k * TKN + c4)
                                 : make_float4(0.f, 0.f, 0.f, 0.f);
            *(float4*)&Vs[r][c4] = v;
        }
        __syncthreads();
#pragma unroll
        for (int kk = 0; kk < 32; kk++) {
            float bv = Vs[kk][tx];
#pragma unroll
            for (int i = 0; i < 8; i++) acc[i] += Ps[ty + 4 * i][kk] * bv;
        }
        __syncthreads();
    }
#pragma unroll
    for (int i = 0; i < 8; i++) {
        int n = n0 + ty + 4 * i;
        if (n < NP1) Oh[(size_t)n * TKN + tx] = acc[i];
    }
}

// ---------------- final copy (drop cls row) ----------------
__global__ void copy_out_k(const float* __restrict__ Y, float* __restrict__ out)
{
    int idx = blockIdx.x * 256 + threadIdx.x;
    if (idx >= BB * NTOK * TKN) return;
    int d = idx % TKN;
    int r = idx / TKN;
    int b = r / NTOK, j = r % NTOK;
    out[idx] = Y[((size_t)(b * NP1 + j + 1)) * TKN + d];
}

// ---------------- driver ----------------
extern "C" void kernel_launch(void* const* d_in, const int* in_sizes, int n_in,
                              void* d_out, int out_size)
{
    const float* x      = (const float*)d_in[0];
    const float* w_enc  = (const float*)d_in[1];
    const float* b_enc  = (const float*)d_in[2];
    const float* cls    = (const float*)d_in[3];
    const float* pos    = (const float*)d_in[4];
    const float* eln_g  = (const float*)d_in[5];
    const float* eln_b  = (const float*)d_in[6];
    const float* wq     = (const float*)d_in[7];
    const float* wk     = (const float*)d_in[8];
    const float* w_hop  = (const float*)d_in[9];
    const float* dec_w  = (const float*)d_in[10];
    const float* dec_b  = (const float*)d_in[11];
    const float* w_dec  = (const float*)d_in[12];
    const float* b_dec  = (const float*)d_in[13];
    float* out = (float*)d_out;

    float *t_, *g_, *q_, *k_, *dq_, *dk_, *h_, *P_;
    cudaGetSymbolAddress((void**)&t_,  g_t);
    cudaGetSymbolAddress((void**)&g_,  g_g);
    cudaGetSymbolAddress((void**)&q_,  g_q);
    cudaGetSymbolAddress((void**)&k_,  g_k);
    cudaGetSymbolAddress((void**)&dq_, g_dq);
    cudaGetSymbolAddress((void**)&dk_, g_dk);
    cudaGetSymbolAddress((void**)&h_,  g_h);
    cudaGetSymbolAddress((void**)&P_,  g_P);

    // allow 73.7KB dynamic smem on the mma kernels (idempotent)
    cudaFuncSetAttribute((const void*)mma_gemm_k<false, true,  false, false>,
                         cudaFuncAttributeMaxDynamicSharedMemorySize, SMEM_GEMM_BYTES);
    cudaFuncSetAttribute((const void*)mma_gemm_k<false, false, false, false>,
                         cudaFuncAttributeMaxDynamicSharedMemorySize, SMEM_GEMM_BYTES);
    cudaFuncSetAttribute((const void*)mma_gemm_k<false, false, true,  false>,
                         cudaFuncAttributeMaxDynamicSharedMemorySize, SMEM_GEMM_BYTES);
    cudaFuncSetAttribute((const void*)mma_gemm_k<true,  false, false, true>,
                         cudaFuncAttributeMaxDynamicSharedMemorySize, SMEM_GEMM_BYTES);

    const dim3 blk(256);
    const dim3 grid768(TKN / 128, (MROWS + 127) / 128);      // (6, 50)
    const dim3 gridHid(HIDN / 128, (MROWS + 127) / 128);     // (24, 50)
    const dim3 gridEnc(TKN / 128, (MENC + 127) / 128);       // (6, 49)

    // encode: enc = x @ w_enc^T + b_enc   (temp in q_)
    mma_gemm_k<false, true, false, false><<<gridEnc, blk, SMEM_GEMM_BYTES>>>(
        x, w_enc, b_enc, q_, MENC, TKN, TKN);
    assemble_t_k<<<(MROWS * TKN + 255) / 256, blk>>>(q_, cls, pos);

    for (int s = 0; s < KSTEPS; s++) {
        ln_kernel<<<MROWS, blk>>>(t_, eln_g, eln_b, g_, 1);
        mma_gemm_k<false, false, false, false><<<grid768, blk, SMEM_GEMM_BYTES>>>(
            g_, wq, nullptr, q_, MROWS, TKN, TKN);
        mma_gemm_k<false, false, false, false><<<grid768, blk, SMEM_GEMM_BYTES>>>(
            g_, wk, nullptr, k_, MROWS, TKN, TKN);
        attn_scores_k<<<dim3(7, 7, BHN), blk>>>(q_, k_, P_);
        softmax_rows_k<<<(BHN * NP1 + 7) / 8, blk>>>(P_);
        attn_av_k<false><<<dim3(7, BHN), blk>>>(P_, k_, dq_);
        attn_av_k<true ><<<dim3(7, BHN), blk>>>(P_, q_, dk_);
        mma_gemm_k<false, false, true, false><<<gridHid, blk, SMEM_GEMM_BYTES>>>(
            g_, w_hop, nullptr, h_, MROWS, HIDN, TKN);
        mma_gemm_k<true, false, false, true><<<grid768, blk, SMEM_GEMM_BYTES>>>(
            dq_, wq, nullptr, t_, MROWS, TKN, TKN);
        mma_gemm_k<true, false, false, true><<<grid768, blk, SMEM_GEMM_BYTES>>>(
            dk_, wk, nullptr, t_, MROWS, TKN, TKN);
        mma_gemm_k<true, false, false, true><<<grid768, blk, SMEM_GEMM_BYTES>>>(
            h_, w_hop, nullptr, t_, MROWS, TKN, HIDN);
    }

    ln_kernel<<<MROWS, blk>>>(t_, dec_w, dec_b, g_, 0);
    mma_gemm_k<false, true, false, false><<<grid768, blk, SMEM_GEMM_BYTES>>>(
        g_, w_dec, b_dec, q_, MROWS, TKN, TKN);
    copy_out_k<<<(BB * NTOK * TKN + 255) / 256, blk>>>(q_, out);
}

// round 3
// speedup vs baseline: 1.9742x; 1.2846x over previous
#include <cuda_runtime.h>
#include <math.h>

// ---------------- problem constants ----------------
#define BB    32
#define NTOK  196
#define NP1   197
#define TKN   768
#define HH    12
#define ZZ    64
#define HIDN  3072
#define MROWS (BB*NP1)    // 6304
#define MENC  (BB*NTOK)   // 6272
#define BHN   (BB*HH)     // 384
#define KSTEPS 12
#define BETA_S 0.125f
#define EPS_LN 1e-5f

// ---------------- scratch (device globals; no allocation) ----------------
__device__ float g_t [MROWS*TKN];
__device__ float g_g [MROWS*TKN];
__device__ float g_q [MROWS*TKN];
__device__ float g_k [MROWS*TKN];
__device__ float g_dq[MROWS*TKN];
__device__ float g_dk[MROWS*TKN];
__device__ float g_h [MROWS*HIDN];
__device__ float g_P [BHN*NP1*NP1];

// ================== tf32 tensor-core GEMM (cp.async 4-stage) ==================
// C[M,N](fp32) = A[M,K] * op(B) (+bias)(+relu)(+accumulate)
// NN=false: B[N,K] (C=A*B^T);  NN=true: B[K,N] (C=A*B)
// BM=256, BN=128, BK=16, 512 threads (16 warps 4x4), warp tile 64x32.

#define STAGES 4
#define BM 256
#define BN 128
#define BK 16
#define AS_STRIDE 20
#define BT_STRIDE 20
#define BNN_STRIDE 136
#define A_STG (BM*AS_STRIDE)      // 5120 floats
#define B_STG 2560                // max(128*20, 16*136)
#define SMEM_GEMM_BYTES (STAGES*(A_STG+B_STG)*4)  // 122880

__device__ __forceinline__ unsigned f2tf(float f) {
    unsigned u;
    asm("cvt.rna.tf32.f32 %0, %1;" : "=r"(u) : "f"(f));
    return u;
}

__device__ __forceinline__ void mma8(float c[4], const unsigned a[4], const unsigned b[2]) {
    asm volatile(
        "mma.sync.aligned.m16n8k8.row.col.f32.tf32.tf32.f32 "
        "{%0,%1,%2,%3}, {%4,%5,%6,%7}, {%8,%9}, {%0,%1,%2,%3};\n"
        : "+f"(c[0]), "+f"(c[1]), "+f"(c[2]), "+f"(c[3])
        : "r"(a[0]), "r"(a[1]), "r"(a[2]), "r"(a[3]), "r"(b[0]), "r"(b[1]));
}

__device__ __forceinline__ void cp16(unsigned dst, const void* src, int sz) {
    asm volatile("cp.async.cg.shared.global [%0], [%1], 16, %2;\n"
                 :: "r"(dst), "l"(src), "r"(sz));
}
__device__ __forceinline__ void cp_commit() {
    asm volatile("cp.async.commit_group;\n");
}
__device__ __forceinline__ void cp_wait2() {
    asm volatile("cp.async.wait_group 2;\n");
}

template<bool NN>
__device__ __forceinline__ void load_stage(
    const float* __restrict__ A, const float* __restrict__ B,
    int M, int N, int K, int m0, int n0, int kt, int tid,
    unsigned sA, unsigned sB)
{
#pragma unroll
    for (int s = 0; s < 2; s++) {
        int id = tid + s * 512;
        int r = id >> 2, c = (id & 3) << 2;
        unsigned dst = sA + (unsigned)(r * AS_STRIDE + c) * 4u;
        bool ok = (m0 + r < M);
        const float* src = ok ? (A + (size_t)(m0 + r) * K + kt + c) : A;
        cp16(dst, src, ok ? 16 : 0);
    }
    if (!NN) {
        int r = tid >> 2, c = (tid & 3) << 2;
        unsigned dst = sB + (unsigned)(r * BT_STRIDE + c) * 4u;
        cp16(dst, B + (size_t)(n0 + r) * K + kt + c, 16);
    } else {
        int r = tid >> 5, c = (tid & 31) << 2;
        unsigned dst = sB + (unsigned)(r * BNN_STRIDE + c) * 4u;
        cp16(dst, B + (size_t)(kt + r) * N + n0 + c, 16);
    }
}

template<bool NN, bool BIAS, bool RELU, bool ACC>
__global__ void __launch_bounds__(512, 1) mma_gemm_k(
    const float* __restrict__ A, const float* __restrict__ B,
    const float* __restrict__ bias, float* __restrict__ C,
    int M, int N, int K)
{
    extern __shared__ float sm[];
    const int tid = threadIdx.x;
    const int m0 = blockIdx.y * BM, n0 = blockIdx.x * BN;
    const int lane = tid & 31, wid = tid >> 5;
    const int wm = (wid & 3) * 64, wn = (wid >> 2) * 32;
    const int g = lane >> 2, tig = lane & 3;

    unsigned smem_u = (unsigned)__cvta_generic_to_shared(sm);
    unsigned sB_base = smem_u + (unsigned)(STAGES * A_STG) * 4u;

    float acc[4][4][4];
#pragma unroll
    for (int mi = 0; mi < 4; mi++)
#pragma unroll
        for (int ni = 0; ni < 4; ni++)
#pragma unroll
            for (int v = 0; v < 4; v++) acc[mi][ni][v] = 0.f;

    const int niter = K >> 4;

    // prologue: prefetch STAGES-1 stages
#pragma unroll
    for (int p = 0; p < STAGES - 1; p++) {
        load_stage<NN>(A, B, M, N, K, m0, n0, p * BK, tid,
                       smem_u + (unsigned)(p * A_STG) * 4u,
                       sB_base + (unsigned)(p * B_STG) * 4u);
        cp_commit();
    }

    for (int it = 0; it < niter; it++) {
        cp_wait2();
        __syncthreads();

        int pf = it + STAGES - 1;
        if (pf < niter) {
            int st = pf & (STAGES - 1);
            load_stage<NN>(A, B, M, N, K, m0, n0, pf * BK, tid,
                           smem_u + (unsigned)(st * A_STG) * 4u,
                           sB_base + (unsigned)(st * B_STG) * 4u);
        }
        cp_commit();

        const float* Ab = sm + (it & (STAGES - 1)) * A_STG;
        const float* Bb = sm + STAGES * A_STG + (it & (STAGES - 1)) * B_STG;
#pragma unroll
        for (int ks = 0; ks < 2; ks++) {
            unsigned af[4][4], bf[4][2];
#pragma unroll
            for (int mi = 0; mi < 4; mi++) {
                const float* p0 = Ab + (wm + mi * 16 + g) * AS_STRIDE + ks * 8 + tig;
                af[mi][0] = f2tf(p0[0]);
                af[mi][1] = f2tf(p0[8 * AS_STRIDE]);
                af[mi][2] = f2tf(p0[4]);
                af[mi][3] = f2tf(p0[8 * AS_STRIDE + 4]);
            }
#pragma unroll
            for (int ni = 0; ni < 4; ni++) {
                if (!NN) {
                    const float* p = Bb + (wn + ni * 8 + g) * BT_STRIDE + ks * 8 + tig;
                    bf[ni][0] = f2tf(p[0]);
                    bf[ni][1] = f2tf(p[4]);
                } else {
                    const float* p = Bb + (ks * 8 + tig) * BNN_STRIDE + wn + ni * 8 + g;
                    bf[ni][0] = f2tf(p[0]);
                    bf[ni][1] = f2tf(p[4 * BNN_STRIDE]);
                }
            }
#pragma unroll
            for (int mi = 0; mi < 4; mi++)
#pragma unroll
                for (int ni = 0; ni < 4; ni++)
                    mma8(acc[mi][ni], af[mi], bf[ni]);
        }
    }

    // epilogue
#pragma unroll
    for (int mi = 0; mi < 4; mi++) {
        int r0 = m0 + wm + mi * 16 + g;
#pragma unroll
        for (int half = 0; half < 2; half++) {
            int row = r0 + half * 8;
            if (row < M) {
                float* crow = C + (size_t)row * N;
#pragma unroll
                for (int ni = 0; ni < 4; ni++) {
                    int col = n0 + wn + ni * 8 + tig * 2;
                    float v0 = acc[mi][ni][half * 2 + 0];
                    float v1 = acc[mi][ni][half * 2 + 1];
                    if (BIAS) { v0 += bias[col]; v1 += bias[col + 1]; }
                    if (RELU) { v0 = fmaxf(v0, 0.f); v1 = fmaxf(v1, 0.f); }
                    if (ACC)  { v0 += crow[col]; v1 += crow[col + 1]; }
                    crow[col] = v0;
                    crow[col + 1] = v1;
                }
            }
        }
    }
}

// ---------------- LayerNorm (scalar or vector gain) ----------------
__device__ __forceinline__ float block_sum_256(float v, float* red)
{
    int lane = threadIdx.x & 31, w = threadIdx.x >> 5;
#pragma unroll
    for (int o = 16; o; o >>= 1) v += __shfl_xor_sync(0xffffffffu, v, o);
    if (lane == 0) red[w] = v;
    __syncthreads();
    if (w == 0) {
        float r = (lane < 8) ? red[lane] : 0.f;
#pragma unroll
        for (int o = 4; o; o >>= 1) r += __shfl_xor_sync(0xffffffffu, r, o);
        if (lane == 0) red[0] = r;
    }
    __syncthreads();
    float out = red[0];
    __syncthreads();
    return out;
}

__global__ void __launch_bounds__(256) ln_kernel(
    const float* __restrict__ X, const float* __restrict__ w,
    const float* __restrict__ bvec, float* __restrict__ Y, int scalar_w)
{
    __shared__ float red[32];
    int row = blockIdx.x;
    const float* x = X + (size_t)row * TKN;
    float* y = Y + (size_t)row * TKN;
    int tid = threadIdx.x;
    float v[3];
    float s = 0.f, ss = 0.f;
#pragma unroll
    for (int i = 0; i < 3; i++) {
        float t = x[tid + i * 256];
        v[i] = t; s += t; ss += t * t;
    }
    float sum  = block_sum_256(s, red);
    float sum2 = block_sum_256(ss, red);
    float mu = sum * (1.f / TKN);
    float var = sum2 * (1.f / TKN) - mu * mu;
    float r = rsqrtf(var + EPS_LN);
#pragma unroll
    for (int i = 0; i < 3; i++) {
        int c = tid + i * 256;
        float gv = (v[i] - mu) * r;
        float wv = scalar_w ? w[0] : w[c];
        y[c] = gv * wv + bvec[c];
    }
}

// ---------------- assemble t = [cls ; enc] + pos ----------------
__global__ void assemble_t_k(const float* __restrict__ enc,
                             const float* __restrict__ cls,
                             const float* __restrict__ pos)
{
    int idx = blockIdx.x * 256 + threadIdx.x;
    if (idx >= MROWS * TKN) return;
    int d = idx % TKN;
    int row = idx / TKN;
    int b = row / NP1, n = row % NP1;
    float v;
    if (n == 0) v = cls[d];
    else        v = enc[((size_t)(b * NTOK + n - 1)) * TKN + d];
    g_t[idx] = v + pos[n * TKN + d];
}

// ---------------- attention scores: P = beta * Qh Kh^T ----------------
__global__ void __launch_bounds__(256) attn_scores_k(
    const float* __restrict__ Q, const float* __restrict__ Kv, float* __restrict__ P)
{
    int bh = blockIdx.z;
    int b = bh / HH, h = bh % HH;
    const float* Qh = Q  + (size_t)b * NP1 * TKN + h * ZZ;
    const float* Kh = Kv + (size_t)b * NP1 * TKN + h * ZZ;
    int q0 = blockIdx.y * 32, k0 = blockIdx.x * 32;
    __shared__ float Qs[32][68];
    __shared__ float Kst[64][33];
    int tid = threadIdx.x;
#pragma unroll
    for (int s = 0; s < 2; s++) {
        int f4 = tid + s * 256;
        int r = f4 >> 4;
        int c4 = (f4 & 15) << 2;
        int gq = q0 + r;
        float4 qv = (gq < NP1) ? *(const float4*)(Qh + (size_t)gq * TKN + c4)
                               : make_float4(0.f, 0.f, 0.f, 0.f);
        *(float4*)&Qs[r][c4] = qv;
        int gk = k0 + r;
        float4 kv = (gk < NP1) ? *(const float4*)(Kh + (size_t)gk * TKN + c4)
                               : make_float4(0.f, 0.f, 0.f, 0.f);
        Kst[c4 + 0][r] = kv.x; Kst[c4 + 1][r] = kv.y;
        Kst[c4 + 2][r] = kv.z; Kst[c4 + 3][r] = kv.w;
    }
    __syncthreads();
    int tx = tid & 15, ty = tid >> 4;
    int r0 = ty * 2, r1 = r0 + 1, c0 = tx * 2, c1 = c0 + 1;
    float a00 = 0.f, a01 = 0.f, a10 = 0.f, a11 = 0.f;
#pragma unroll
    for (int z = 0; z < ZZ; z++) {
        float qa = Qs[r0][z], qb = Qs[r1][z];
        float ka = Kst[z][c0], kb = Kst[z][c1];
        a00 += qa * ka; a01 += qa * kb; a10 += qb * ka; a11 += qb * kb;
    }
    float* Pp = P + (size_t)bh * NP1 * NP1;
    int gq0 = q0 + r0, gq1 = q0 + r1, gk0 = k0 + c0, gk1 = k0 + c1;
    if (gq0 < NP1) {
        if (gk0 < NP1) Pp[(size_t)gq0 * NP1 + gk0] = BETA_S * a00;
        if (gk1 < NP1) Pp[(size_t)gq0 * NP1 + gk1] = BETA_S * a01;
    }
    if (gq1 < NP1) {
        if (gk0 < NP1) Pp[(size_t)gq1 * NP1 + gk0] = BETA_S * a10;
        if (gk1 < NP1) Pp[(size_t)gq1 * NP1 + gk1] = BETA_S * a11;
    }
}

// ---------------- row softmax over P ----------------
__global__ void __launch_bounds__(256) softmax_rows_k(float* __restrict__ P)
{
    int row = blockIdx.x * 8 + (threadIdx.x >> 5);
    if (row >= BHN * NP1) return;
    int lane = threadIdx.x & 31;
    float* p = P + (size_t)row * NP1;
    float vals[7];
    float m = -1e30f;
#pragma unroll
    for (int i = 0; i < 7; i++) {
        int c = lane + i * 32;
        float v = (c < NP1) ? p[c] : -1e30f;
        vals[i] = v;
        m = fmaxf(m, v);
    }
#pragma unroll
    for (int o = 16; o; o >>= 1) m = fmaxf(m, __shfl_xor_sync(0xffffffffu, m, o));
    float s = 0.f;
#pragma unroll
    for (int i = 0; i < 7; i++) {
        int c = lane + i * 32;
        float e = (c < NP1) ? expf(vals[i] - m) : 0.f;
        vals[i] = e; s += e;
    }
#pragma unroll
    for (int o = 16; o; o >>= 1) s += __shfl_xor_sync(0xffffffffu, s, o);
    float inv = 1.f / s;
#pragma unroll
    for (int i = 0; i < 7; i++) {
        int c = lane + i * 32;
        if (c < NP1) p[c] = vals[i] * inv;
    }
}

// ---------------- batched PV ----------------
template<bool TRANSP>
__global__ void __launch_bounds__(256) attn_av_k(
    const float* __restrict__ P, const float* __restrict__ V, float* __restrict__ Out)
{
    int bh = blockIdx.y;
    int b = bh / HH, h = bh % HH;
    const float* Pp = P + (size_t)bh * NP1 * NP1;
    const float* Vh = V   + (size_t)b * NP1 * TKN + h * ZZ;
    float*       Oh = Out + (size_t)b * NP1 * TKN + h * ZZ;
    int n0 = blockIdx.x * 32;
    __shared__ float Ps[32][33];
    __shared__ float Vs[32][64];
    int tid = threadIdx.x;
    int tx = tid & 63, ty = tid >> 6;
    float acc[8];
#pragma unroll
    for (int i = 0; i < 8; i++) acc[i] = 0.f;

    for (int kb = 0; kb < NP1; kb += 32) {
#pragma unroll
        for (int s = 0; s < 4; s++) {
            int idx = tid + s * 256;
            int r = idx >> 5, kk = idx & 31;
            float v = 0.f;
            int n = n0 + r, k = kb + kk;
            if (n < NP1 && k < NP1)
                v = TRANSP ? Pp[(size_t)k * NP1 + n] : Pp[(size_t)n * NP1 + k];
            Ps[r][kk] = v;
        }
#pragma unroll
        for (int s = 0; s < 2; s++) {
            int f4 = tid + s * 256;
            int r = f4 >> 4, c4 = (f4 & 15) << 2;
            int k = kb + r;
            float4 v = (k < NP1) ? *(const float4*)(Vh + (size_t)k * TKN + c4)
                                 : make_float4(0.f, 0.f, 0.f, 0.f);
            *(float4*)&Vs[r][c4] = v;
        }
        __syncthreads();
#pragma unroll
        for (int kk = 0; kk < 32; kk++) {
            float bv = Vs[kk][tx];
#pragma unroll
            for (int i = 0; i < 8; i++) acc[i] += Ps[ty + 4 * i][kk] * bv;
        }
        __syncthreads();
    }
#pragma unroll
    for (int i = 0; i < 8; i++) {
        int n = n0 + ty + 4 * i;
        if (n < NP1) Oh[(size_t)n * TKN + tx] = acc[i];
    }
}

// ---------------- final copy (drop cls row) ----------------
__global__ void copy_out_k(const float* __restrict__ Y, float* __restrict__ out)
{
    int idx = blockIdx.x * 256 + threadIdx.x;
    if (idx >= BB * NTOK * TKN) return;
    int d = idx % TKN;
    int r = idx / TKN;
    int b = r / NTOK, j = r % NTOK;
    out[idx] = Y[((size_t)(b * NP1 + j + 1)) * TKN + d];
}

// ---------------- driver ----------------
extern "C" void kernel_launch(void* const* d_in, const int* in_sizes, int n_in,
                              void* d_out, int out_size)
{
    const float* x      = (const float*)d_in[0];
    const float* w_enc  = (const float*)d_in[1];
    const float* b_enc  = (const float*)d_in[2];
    const float* cls    = (const float*)d_in[3];
    const float* pos    = (const float*)d_in[4];
    const float* eln_g  = (const float*)d_in[5];
    const float* eln_b  = (const float*)d_in[6];
    const float* wq     = (const float*)d_in[7];
    const float* wk     = (const float*)d_in[8];
    const float* w_hop  = (const float*)d_in[9];
    const float* dec_w  = (const float*)d_in[10];
    const float* dec_b  = (const float*)d_in[11];
    const float* w_dec  = (const float*)d_in[12];
    const float* b_dec  = (const float*)d_in[13];
    float* out = (float*)d_out;

    float *t_, *g_, *q_, *k_, *dq_, *dk_, *h_, *P_;
    cudaGetSymbolAddress((void**)&t_,  g_t);
    cudaGetSymbolAddress((void**)&g_,  g_g);
    cudaGetSymbolAddress((void**)&q_,  g_q);
    cudaGetSymbolAddress((void**)&k_,  g_k);
    cudaGetSymbolAddress((void**)&dq_, g_dq);
    cudaGetSymbolAddress((void**)&dk_, g_dk);
    cudaGetSymbolAddress((void**)&h_,  g_h);
    cudaGetSymbolAddress((void**)&P_,  g_P);

    cudaFuncSetAttribute((const void*)mma_gemm_k<false, true,  false, false>,
                         cudaFuncAttributeMaxDynamicSharedMemorySize, SMEM_GEMM_BYTES);
    cudaFuncSetAttribute((const void*)mma_gemm_k<false, false, false, false>,
                         cudaFuncAttributeMaxDynamicSharedMemorySize, SMEM_GEMM_BYTES);
    cudaFuncSetAttribute((const void*)mma_gemm_k<false, false, true,  false>,
                         cudaFuncAttributeMaxDynamicSharedMemorySize, SMEM_GEMM_BYTES);
    cudaFuncSetAttribute((const void*)mma_gemm_k<true,  false, false, true>,
                         cudaFuncAttributeMaxDynamicSharedMemorySize, SMEM_GEMM_BYTES);

    const dim3 blk512(512);
    const dim3 blk(256);
    const int  mtiles = (MROWS + BM - 1) / BM;   // 25
    const int  mtE    = (MENC  + BM - 1) / BM;   // 25
    const dim3 grid768(TKN / BN, mtiles);        // (6, 25)
    const dim3 gridHid(HIDN / BN, mtiles);       // (24, 25)
    const dim3 gridEnc(TKN / BN, mtE);           // (6, 25)

    // encode: enc = x @ w_enc^T + b_enc   (temp in q_)
    mma_gemm_k<false, true, false, false><<<gridEnc, blk512, SMEM_GEMM_BYTES>>>(
        x, w_enc, b_enc, q_, MENC, TKN, TKN);
    assemble_t_k<<<(MROWS * TKN + 255) / 256, blk>>>(q_, cls, pos);

    for (int s = 0; s < KSTEPS; s++) {
        ln_kernel<<<MROWS, blk>>>(t_, eln_g, eln_b, g_, 1);
        mma_gemm_k<false, false, false, false><<<grid768, blk512, SMEM_GEMM_BYTES>>>(
            g_, wq, nullptr, q_, MROWS, TKN, TKN);
        mma_gemm_k<false, false, false, false><<<grid768, blk512, SMEM_GEMM_BYTES>>>(
            g_, wk, nullptr, k_, MROWS, TKN, TKN);
        attn_scores_k<<<dim3(7, 7, BHN), blk>>>(q_, k_, P_);
        softmax_rows_k<<<(BHN * NP1 + 7) / 8, blk>>>(P_);
        attn_av_k<false><<<dim3(7, BHN), blk>>>(P_, k_, dq_);
        attn_av_k<true ><<<dim3(7, BHN), blk>>>(P_, q_, dk_);
        mma_gemm_k<false, false, true, false><<<gridHid, blk512, SMEM_GEMM_BYTES>>>(
            g_, w_hop, nullptr, h_, MROWS, HIDN, TKN);
        mma_gemm_k<true, false, false, true><<<grid768, blk512, SMEM_GEMM_BYTES>>>(
            dq_, wq, nullptr, t_, MROWS, TKN, TKN);
        mma_gemm_k<true, false, false, true><<<grid768, blk512, SMEM_GEMM_BYTES>>>(
            dk_, wk, nullptr, t_, MROWS, TKN, TKN);
        mma_gemm_k<true, false, false, true><<<grid768, blk512, SMEM_GEMM_BYTES>>>(
            h_, w_hop, nullptr, t_, MROWS, TKN, HIDN);
    }

    ln_kernel<<<MROWS, blk>>>(t_, dec_w, dec_b, g_, 0);
    mma_gemm_k<false, true, false, false><<<grid768, blk512, SMEM_GEMM_BYTES>>>(
        g_, w_dec, b_dec, q_, MROWS, TKN, TKN);
    copy_out_k<<<(BB * NTOK * TKN + 255) / 256, blk>>>(q_, out);
}

// round 4
// speedup vs baseline: 3.2063x; 1.6242x over previous
#include <cuda_runtime.h>
#include <math.h>

// ---------------- problem constants ----------------
#define BB    32
#define NTOK  196
#define NP1   197
#define TKN   768
#define HH    12
#define ZZ    64
#define HIDN  3072
#define MROWS (BB*NP1)    // 6304
#define MENC  (BB*NTOK)   // 6272
#define BHN   (BB*HH)     // 384
#define KSTEPS 12
#define BETA_S 0.125f
#define EPS_LN 1e-5f

// ---------------- scratch (device globals; no allocation) ----------------
__device__ float    g_t [MROWS*TKN];    // fp32 state
__device__ unsigned g_g [MROWS*TKN];    // tf32 bits
__device__ unsigned g_q [MROWS*TKN];    // tf32 bits
__device__ unsigned g_k [MROWS*TKN];    // tf32 bits
__device__ float    g_dq[MROWS*TKN];    // tf32 bits (steps) / fp32 (enc+dec out)
__device__ unsigned g_dk[MROWS*TKN];    // tf32 bits
__device__ unsigned g_h [MROWS*HIDN];   // tf32 bits
__device__ float    g_P [BHN*NP1*NP1];  // fp32 scores -> tf32 bits after softmax
// pre-converted tf32 operands
__device__ unsigned g_wqt [TKN*TKN];
__device__ unsigned g_wkt [TKN*TKN];
__device__ unsigned g_hopt[HIDN*TKN];
__device__ unsigned g_enct[TKN*TKN];
__device__ unsigned g_dect[TKN*TKN];
__device__ unsigned g_xt  [MENC*TKN];

__device__ __forceinline__ unsigned f2tf(float f) {
    unsigned u;
    asm("cvt.rna.tf32.f32 %0, %1;" : "=r"(u) : "f"(f));
    return u;
}

__device__ __forceinline__ void mma8(float c[4], const unsigned a[4], const unsigned b[2]) {
    asm volatile(
        "mma.sync.aligned.m16n8k8.row.col.f32.tf32.tf32.f32 "
        "{%0,%1,%2,%3}, {%4,%5,%6,%7}, {%8,%9}, {%0,%1,%2,%3};\n"
        : "+f"(c[0]), "+f"(c[1]), "+f"(c[2]), "+f"(c[3])
        : "r"(a[0]), "r"(a[1]), "r"(a[2]), "r"(a[3]), "r"(b[0]), "r"(b[1]));
}

__global__ void cvt_tf32_k(const float* __restrict__ in, unsigned* __restrict__ out, int n)
{
    int i = blockIdx.x * 256 + threadIdx.x;
    if (i < n) out[i] = f2tf(in[i]);
}

// ================== tf32 tensor-core GEMM (cp.async, BK=32, 3-stage) ==================
// C[M,N] = A[M,K]*op(B) (+bias)(+relu)(+acc); A,B hold tf32 bits.
// NN=false: B[N,K]; NN=true: B[K,N].  OTF: write output as tf32 bits.
#define STAGES 3
#define BM 256
#define BN 128
#define BK 32
#define AS_STRIDE 36
#define BT_STRIDE 36
#define BNN_STRIDE 136
#define A_STG (BM*AS_STRIDE)          // 9216
#define B_STG 4608                    // max(128*36, 32*136=4352)
#define SMEM_GEMM_BYTES (STAGES*(A_STG+B_STG)*4)   // 165888

__device__ __forceinline__ void cp16(unsigned dst, const void* src, int sz) {
    asm volatile("cp.async.cg.shared.global [%0], [%1], 16, %2;\n"
                 :: "r"(dst), "l"(src), "r"(sz));
}
__device__ __forceinline__ void cp_commit() { asm volatile("cp.async.commit_group;\n"); }
__device__ __forceinline__ void cp_wait1()  { asm volatile("cp.async.wait_group 1;\n"); }

template<bool NN>
__device__ __forceinline__ void load_stage(
    const unsigned* __restrict__ A, const unsigned* __restrict__ B,
    int M, int N, int K, int m0, int n0, int kt, int tid,
    unsigned sA, unsigned sB)
{
#pragma unroll
    for (int s = 0; s < 4; s++) {
        int id = tid + s * 512;
        int r = id >> 3, c = (id & 7) << 2;
        unsigned dst = sA + (unsigned)(r * AS_STRIDE + c) * 4u;
        bool ok = (m0 + r < M);
        const unsigned* src = ok ? (A + (size_t)(m0 + r) * K + kt + c) : A;
        cp16(dst, src, ok ? 16 : 0);
    }
#pragma unroll
    for (int s = 0; s < 2; s++) {
        int id = tid + s * 512;
        if (!NN) {
            int r = id >> 3, c = (id & 7) << 2;
            unsigned dst = sB + (unsigned)(r * BT_STRIDE + c) * 4u;
            cp16(dst, B + (size_t)(n0 + r) * K + kt + c, 16);
        } else {
            int r = id >> 5, c = (id & 31) << 2;
            unsigned dst = sB + (unsigned)(r * BNN_STRIDE + c) * 4u;
            cp16(dst, B + (size_t)(kt + r) * N + n0 + c, 16);
        }
    }
}

template<bool NN, bool BIAS, bool RELU, bool ACC, bool OTF>
__global__ void __launch_bounds__(512, 1) mma_gemm_k(
    const unsigned* __restrict__ A, const unsigned* __restrict__ B,
    const float* __restrict__ bias, float* __restrict__ C,
    int M, int N, int K)
{
    extern __shared__ unsigned sm[];
    const int tid = threadIdx.x;
    const int m0 = blockIdx.y * BM, n0 = blockIdx.x * BN;
    const int lane = tid & 31, wid = tid >> 5;
    const int wm = (wid & 3) * 64, wn = (wid >> 2) * 32;
    const int g = lane >> 2, tig = lane & 3;

    unsigned smem_u = (unsigned)__cvta_generic_to_shared(sm);
    unsigned sB_base = smem_u + (unsigned)(STAGES * A_STG) * 4u;

    float acc[4][4][4];
#pragma unroll
    for (int mi = 0; mi < 4; mi++)
#pragma unroll
        for (int ni = 0; ni < 4; ni++)
#pragma unroll
            for (int v = 0; v < 4; v++) acc[mi][ni][v] = 0.f;

    const int niter = K >> 5;

#pragma unroll
    for (int p = 0; p < STAGES - 1; p++) {
        load_stage<NN>(A, B, M, N, K, m0, n0, p * BK, tid,
                       smem_u + (unsigned)(p * A_STG) * 4u,
                       sB_base + (unsigned)(p * B_STG) * 4u);
        cp_commit();
    }

    int stc = 0;
    for (int it = 0; it < niter; it++) {
        cp_wait1();
        __syncthreads();

        int pf = it + STAGES - 1;
        if (pf < niter) {
            int st = pf % STAGES;
            load_stage<NN>(A, B, M, N, K, m0, n0, pf * BK, tid,
                           smem_u + (unsigned)(st * A_STG) * 4u,
                           sB_base + (unsigned)(st * B_STG) * 4u);
        }
        cp_commit();

        const unsigned* Ab = sm + stc * A_STG;
        const unsigned* Bb = sm + STAGES * A_STG + stc * B_STG;
        stc = (stc + 1 == STAGES) ? 0 : stc + 1;
#pragma unroll
        for (int ks = 0; ks < 4; ks++) {
            unsigned af[4][4], bf[4][2];
#pragma unroll
            for (int mi = 0; mi < 4; mi++) {
                const unsigned* p0 = Ab + (wm + mi * 16 + g) * AS_STRIDE + ks * 8 + tig;
                af[mi][0] = p0[0];
                af[mi][1] = p0[8 * AS_STRIDE];
                af[mi][2] = p0[4];
                af[mi][3] = p0[8 * AS_STRIDE + 4];
            }
#pragma unroll
            for (int ni = 0; ni < 4; ni++) {
                if (!NN) {
                    const unsigned* p = Bb + (wn + ni * 8 + g) * BT_STRIDE + ks * 8 + tig;
                    bf[ni][0] = p[0];
                    bf[ni][1] = p[4];
                } else {
                    const unsigned* p = Bb + (ks * 8 + tig) * BNN_STRIDE + wn + ni * 8 + g;
                    bf[ni][0] = p[0];
                    bf[ni][1] = p[4 * BNN_STRIDE];
                }
            }
#pragma unroll
            for (int mi = 0; mi < 4; mi++)
#pragma unroll
                for (int ni = 0; ni < 4; ni++)
                    mma8(acc[mi][ni], af[mi], bf[ni]);
        }
    }

#pragma unroll
    for (int mi = 0; mi < 4; mi++) {
#pragma unroll
        for (int half = 0; half < 2; half++) {
            int row = m0 + wm + mi * 16 + g + half * 8;
            if (row < M) {
                float* crow = C + (size_t)row * N;
#pragma unroll
                for (int ni = 0; ni < 4; ni++) {
                    int col = n0 + wn + ni * 8 + tig * 2;
                    float v0 = acc[mi][ni][half * 2 + 0];
                    float v1 = acc[mi][ni][half * 2 + 1];
                    if (BIAS) { v0 += bias[col]; v1 += bias[col + 1]; }
                    if (RELU) { v0 = fmaxf(v0, 0.f); v1 = fmaxf(v1, 0.f); }
                    if (ACC)  { v0 += crow[col]; v1 += crow[col + 1]; }
                    if (OTF)  { crow[col] = __uint_as_float(f2tf(v0));
                                crow[col + 1] = __uint_as_float(f2tf(v1)); }
                    else      { crow[col] = v0; crow[col + 1] = v1; }
                }
            }
        }
    }
}

// ---------------- LayerNorm (writes tf32 bits) ----------------
__device__ __forceinline__ float block_sum_256(float v, float* red)
{
    int lane = threadIdx.x & 31, w = threadIdx.x >> 5;
#pragma unroll
    for (int o = 16; o; o >>= 1) v += __shfl_xor_sync(0xffffffffu, v, o);
    if (lane == 0) red[w] = v;
    __syncthreads();
    if (w == 0) {
        float r = (lane < 8) ? red[lane] : 0.f;
#pragma unroll
        for (int o = 4; o; o >>= 1) r += __shfl_xor_sync(0xffffffffu, r, o);
        if (lane == 0) red[0] = r;
    }
    __syncthreads();
    float out = red[0];
    __syncthreads();
    return out;
}

__global__ void __launch_bounds__(256) ln_kernel(
    const float* __restrict__ X, const float* __restrict__ w,
    const float* __restrict__ bvec, unsigned* __restrict__ Y, int scalar_w)
{
    __shared__ float red[32];
    int row = blockIdx.x;
    const float* x = X + (size_t)row * TKN;
    unsigned* y = Y + (size_t)row * TKN;
    int tid = threadIdx.x;
    float v[3];
    float s = 0.f, ss = 0.f;
#pragma unroll
    for (int i = 0; i < 3; i++) {
        float t = x[tid + i * 256];
        v[i] = t; s += t; ss += t * t;
    }
    float sum  = block_sum_256(s, red);
    float sum2 = block_sum_256(ss, red);
    float mu = sum * (1.f / TKN);
    float var = sum2 * (1.f / TKN) - mu * mu;
    float r = rsqrtf(var + EPS_LN);
#pragma unroll
    for (int i = 0; i < 3; i++) {
        int c = tid + i * 256;
        float gv = (v[i] - mu) * r;
        float wv = scalar_w ? w[0] : w[c];
        y[c] = f2tf(gv * wv + bvec[c]);
    }
}

// ---------------- assemble t = [cls ; enc] + pos ----------------
__global__ void assemble_t_k(const float* __restrict__ enc,
                             const float* __restrict__ cls,
                             const float* __restrict__ pos)
{
    int idx = blockIdx.x * 256 + threadIdx.x;
    if (idx >= MROWS * TKN) return;
    int d = idx % TKN;
    int row = idx / TKN;
    int b = row / NP1, n = row % NP1;
    float v;
    if (n == 0) v = cls[d];
    else        v = enc[((size_t)(b * NTOK + n - 1)) * TKN + d];
    g_t[idx] = v + pos[n * TKN + d];
}

// ---------------- attention scores via mma: P = beta * Qh Kh^T ----------------
// grid (4 ktile, 4 qtile, BHN), 128 threads; Q,K hold tf32 bits.
__global__ void __launch_bounds__(128) attn_score_mma_k(
    const unsigned* __restrict__ Q, const unsigned* __restrict__ Kv, float* __restrict__ P)
{
    __shared__ unsigned Qs[64 * 68];
    __shared__ unsigned Ks[64 * 68];
    int bh = blockIdx.z, b = bh / HH, h = bh % HH;
    const unsigned* Qb = Q  + (size_t)b * NP1 * TKN + h * ZZ;
    const unsigned* Kb = Kv + (size_t)b * NP1 * TKN + h * ZZ;
    int q0 = blockIdx.y * 64, k0 = blockIdx.x * 64;
    int tid = threadIdx.x;
#pragma unroll
    for (int s = 0; s < 8; s++) {
        int id = tid + s * 128;
        int r = id >> 4, c4 = (id & 15) << 2;
        uint4 z = make_uint4(0u, 0u, 0u, 0u);
        uint4 qv = (q0 + r < NP1) ? *(const uint4*)(Qb + (size_t)(q0 + r) * TKN + c4) : z;
        *(uint4*)&Qs[r * 68 + c4] = qv;
        uint4 kv = (k0 + r < NP1) ? *(const uint4*)(Kb + (size_t)(k0 + r) * TKN + c4) : z;
        *(uint4*)&Ks[r * 68 + c4] = kv;
    }
    __syncthreads();
    int lane = tid & 31, wid = tid >> 5;
    int wm = (wid & 1) * 32, wn = (wid >> 1) * 32;
    int g = lane >> 2, tig = lane & 3;
    float acc[2][4][4];
#pragma unroll
    for (int mi = 0; mi < 2; mi++)
#pragma unroll
        for (int ni = 0; ni < 4; ni++)
#pragma unroll
            for (int v = 0; v < 4; v++) acc[mi][ni][v] = 0.f;
#pragma unroll
    for (int ks = 0; ks < 8; ks++) {
        unsigned af[2][4], bf[4][2];
#pragma unroll
        for (int mi = 0; mi < 2; mi++) {
            const unsigned* p = Qs + (wm + mi * 16 + g) * 68 + ks * 8 + tig;
            af[mi][0] = p[0]; af[mi][1] = p[8 * 68]; af[mi][2] = p[4]; af[mi][3] = p[8 * 68 + 4];
        }
#pragma unroll
        for (int ni = 0; ni < 4; ni++) {
            const unsigned* p = Ks + (wn + ni * 8 + g) * 68 + ks * 8 + tig;
            bf[ni][0] = p[0]; bf[ni][1] = p[4];
        }
#pragma unroll
        for (int mi = 0; mi < 2; mi++)
#pragma unroll
            for (int ni = 0; ni < 4; ni++)
                mma8(acc[mi][ni], af[mi], bf[ni]);
    }
    float* Pp = P + (size_t)bh * NP1 * NP1;
#pragma unroll
    for (int mi = 0; mi < 2; mi++)
#pragma unroll
        for (int half = 0; half < 2; half++) {
            int row = q0 + wm + mi * 16 + g + half * 8;
            if (row < NP1) {
#pragma unroll
                for (int ni = 0; ni < 4; ni++) {
                    int col = k0 + wn + ni * 8 + tig * 2;
                    if (col < NP1)     Pp[(size_t)row * NP1 + col]     = BETA_S * acc[mi][ni][half * 2];
                    if (col + 1 < NP1) Pp[(size_t)row * NP1 + col + 1] = BETA_S * acc[mi][ni][half * 2 + 1];
                }
            }
        }
}

// ---------------- row softmax over P (writes tf32 bits) ----------------
__global__ void __launch_bounds__(256) softmax_rows_k(float* __restrict__ P)
{
    int row = blockIdx.x * 8 + (threadIdx.x >> 5);
    if (row >= BHN * NP1) return;
    int lane = threadIdx.x & 31;
    float* p = P + (size_t)row * NP1;
    float vals[7];
    float m = -1e30f;
#pragma unroll
    for (int i = 0; i < 7; i++) {
        int c = lane + i * 32;
        float v = (c < NP1) ? p[c] : -1e30f;
        vals[i] = v;
        m = fmaxf(m, v);
    }
#pragma unroll
    for (int o = 16; o; o >>= 1) m = fmaxf(m, __shfl_xor_sync(0xffffffffu, m, o));
    float s = 0.f;
#pragma unroll
    for (int i = 0; i < 7; i++) {
        int c = lane + i * 32;
        float e = (c < NP1) ? expf(vals[i] - m) : 0.f;
        vals[i] = e; s += e;
    }
#pragma unroll
    for (int o = 16; o; o >>= 1) s += __shfl_xor_sync(0xffffffffu, s, o);
    float inv = 1.f / s;
#pragma unroll
    for (int i = 0; i < 7; i++) {
        int c = lane + i * 32;
        if (c < NP1) p[c] = __uint_as_float(f2tf(vals[i] * inv));
    }
}

// ---------------- attention PV via mma ----------------
// TRANSP=false: Out = P @ V ; TRANSP=true: Out = P^T @ V.  Output tf32 bits.
// grid (4 mtile, BHN), 128 threads (4 warps, warp tile 16x64).
template<bool TRANSP>
__global__ void __launch_bounds__(128) attn_av_mma_k(
    const float* __restrict__ Pb, const unsigned* __restrict__ V, unsigned* __restrict__ Out)
{
    __shared__ unsigned Ps[64 * 36];
    __shared__ unsigned Vs[32 * 72];
    int bh = blockIdx.y, b = bh / HH, h = bh % HH;
    const float* Pp = Pb + (size_t)bh * NP1 * NP1;
    const unsigned* Vb = V + (size_t)b * NP1 * TKN + h * ZZ;
    unsigned* Ob = Out + (size_t)b * NP1 * TKN + h * ZZ;
    int m0 = blockIdx.x * 64;
    int tid = threadIdx.x, lane = tid & 31, wid = tid >> 5;
    int g = lane >> 2, tig = lane & 3, wm = wid * 16;
    float acc[8][4];
#pragma unroll
    for (int ni = 0; ni < 8; ni++)
#pragma unroll
        for (int v = 0; v < 4; v++) acc[ni][v] = 0.f;

    for (int kb = 0; kb < NP1; kb += 32) {
        __syncthreads();
#pragma unroll
        for (int s = 0; s < 16; s++) {
            int id = tid + s * 128;
            int r, kk;
            if (!TRANSP) { r = id >> 5; kk = id & 31; }
            else         { r = id & 63; kk = id >> 6; }
            float v = 0.f;
            int mg = m0 + r, kg = kb + kk;
            if (mg < NP1 && kg < NP1)
                v = TRANSP ? Pp[(size_t)kg * NP1 + mg] : Pp[(size_t)mg * NP1 + kg];
            Ps[r * 36 + kk] = __float_as_uint(v);
        }
#pragma unroll
        for (int s = 0; s < 4; s++) {
            int id = tid + s * 128;
            int r = id >> 4, c4 = (id & 15) << 2;
            uint4 v = (kb + r < NP1) ? *(const uint4*)(Vb + (size_t)(kb + r) * TKN + c4)
                                     : make_uint4(0u, 0u, 0u, 0u);
            *(uint4*)&Vs[r * 72 + c4] = v;
        }
        __syncthreads();
#pragma unroll
        for (int ks = 0; ks < 4; ks++) {
            unsigned af[4], bf[8][2];
            const unsigned* pa = Ps + (wm + g) * 36 + ks * 8 + tig;
            af[0] = pa[0]; af[1] = pa[8 * 36]; af[2] = pa[4]; af[3] = pa[8 * 36 + 4];
#pragma unroll
            for (int ni = 0; ni < 8; ni++) {
                const unsigned* pb = Vs + (ks * 8 + tig) * 72 + ni * 8 + g;
                bf[ni][0] = pb[0]; bf[ni][1] = pb[4 * 72];
            }
#pragma unroll
            for (int ni = 0; ni < 8; ni++)
                mma8(acc[ni], af, bf[ni]);
        }
    }
#pragma unroll
    for (int half = 0; half < 2; half++) {
        int row = m0 + wm + g + half * 8;
        if (row < NP1) {
            unsigned* orow = Ob + (size_t)row * TKN;
#pragma unroll
            for (int ni = 0; ni < 8; ni++) {
                int col = ni * 8 + tig * 2;
                orow[col]     = f2tf(acc[ni][half * 2]);
                orow[col + 1] = f2tf(acc[ni][half * 2 + 1]);
            }
        }
    }
}

// ---------------- final copy (drop cls row) ----------------
__global__ void copy_out_k(const float* __restrict__ Y, float* __restrict__ out)
{
    int idx = blockIdx.x * 256 + threadIdx.x;
    if (idx >= BB * NTOK * TKN) return;
    int d = idx % TKN;
    int r = idx / TKN;
    int b = r / NTOK, j = r % NTOK;
    out[idx] = Y[((size_t)(b * NP1 + j + 1)) * TKN + d];
}

// ---------------- driver ----------------
extern "C" void kernel_launch(void* const* d_in, const int* in_sizes, int n_in,
                              void* d_out, int out_size)
{
    const float* x      = (const float*)d_in[0];
    const float* w_enc  = (const float*)d_in[1];
    const float* b_enc  = (const float*)d_in[2];
    const float* cls    = (const float*)d_in[3];
    const float* pos    = (const float*)d_in[4];
    const float* eln_g  = (const float*)d_in[5];
    const float* eln_b  = (const float*)d_in[6];
    const float* wq     = (const float*)d_in[7];
    const float* wk     = (const float*)d_in[8];
    const float* w_hop  = (const float*)d_in[9];
    const float* dec_w  = (const float*)d_in[10];
    const float* dec_b  = (const float*)d_in[11];
    const float* w_dec  = (const float*)d_in[12];
    const float* b_dec  = (const float*)d_in[13];
    float* out = (float*)d_out;

    float *t_, *dq_, *P_;
    unsigned *g_, *q_, *k_, *dk_, *h_;
    unsigned *wqt_, *wkt_, *hopt_, *enct_, *dect_, *xt_;
    cudaGetSymbolAddress((void**)&t_,   g_t);
    cudaGetSymbolAddress((void**)&g_,   g_g);
    cudaGetSymbolAddress((void**)&q_,   g_q);
    cudaGetSymbolAddress((void**)&k_,   g_k);
    cudaGetSymbolAddress((void**)&dq_,  g_dq);
    cudaGetSymbolAddress((void**)&dk_,  g_dk);
    cudaGetSymbolAddress((void**)&h_,   g_h);
    cudaGetSymbolAddress((void**)&P_,   g_P);
    cudaGetSymbolAddress((void**)&wqt_, g_wqt);
    cudaGetSymbolAddress((void**)&wkt_, g_wkt);
    cudaGetSymbolAddress((void**)&hopt_,g_hopt);
    cudaGetSymbolAddress((void**)&enct_,g_enct);
    cudaGetSymbolAddress((void**)&dect_,g_dect);
    cudaGetSymbolAddress((void**)&xt_,  g_xt);

    cudaFuncSetAttribute((const void*)mma_gemm_k<false, true,  false, false, false>,
                         cudaFuncAttributeMaxDynamicSharedMemorySize, SMEM_GEMM_BYTES);
    cudaFuncSetAttribute((const void*)mma_gemm_k<false, false, false, false, true>,
                         cudaFuncAttributeMaxDynamicSharedMemorySize, SMEM_GEMM_BYTES);
    cudaFuncSetAttribute((const void*)mma_gemm_k<false, false, true,  false, true>,
                         cudaFuncAttributeMaxDynamicSharedMemorySize, SMEM_GEMM_BYTES);
    cudaFuncSetAttribute((const void*)mma_gemm_k<true,  false, false, true,  false>,
                         cudaFuncAttributeMaxDynamicSharedMemorySize, SMEM_GEMM_BYTES);

    const dim3 blk512(512);
    const dim3 blk(256);
    const int  mtiles = (MROWS + BM - 1) / BM;   // 25
    const int  mtE    = (MENC  + BM - 1) / BM;   // 25
    const dim3 grid768(TKN / BN, mtiles);
    const dim3 gridHid(HIDN / BN, mtiles);
    const dim3 gridEnc(TKN / BN, mtE);

    // one-time tf32 conversions
    cvt_tf32_k<<<(TKN*TKN + 255) / 256, blk>>>(w_enc, enct_, TKN*TKN);
    cvt_tf32_k<<<(TKN*TKN + 255) / 256, blk>>>(wq,    wqt_,  TKN*TKN);
    cvt_tf32_k<<<(TKN*TKN + 255) / 256, blk>>>(wk,    wkt_,  TKN*TKN);
    cvt_tf32_k<<<(HIDN*TKN + 255) / 256, blk>>>(w_hop, hopt_, HIDN*TKN);
    cvt_tf32_k<<<(TKN*TKN + 255) / 256, blk>>>(w_dec, dect_, TKN*TKN);
    cvt_tf32_k<<<(MENC*TKN + 255) / 256, blk>>>(x,     xt_,   MENC*TKN);

    // encode (fp32 out into dq_), assemble
    mma_gemm_k<false, true, false, false, false><<<gridEnc, blk512, SMEM_GEMM_BYTES>>>(
        xt_, enct_, b_enc, dq_, MENC, TKN, TKN);
    assemble_t_k<<<(MROWS * TKN + 255) / 256, blk>>>(dq_, cls, pos);

    for (int s = 0; s < KSTEPS; s++) {
        ln_kernel<<<MROWS, blk>>>(t_, eln_g, eln_b, g_, 1);
        mma_gemm_k<false, false, false, false, true><<<grid768, blk512, SMEM_GEMM_BYTES>>>(
            g_, wqt_, nullptr, (float*)q_, MROWS, TKN, TKN);
        mma_gemm_k<false, false, false, false, true><<<grid768, blk512, SMEM_GEMM_BYTES>>>(
            g_, wkt_, nullptr, (float*)k_, MROWS, TKN, TKN);
        attn_score_mma_k<<<dim3(4, 4, BHN), dim3(128)>>>(q_, k_, P_);
        softmax_rows_k<<<(BHN * NP1 + 7) / 8, blk>>>(P_);
        attn_av_mma_k<false><<<dim3(4, BHN), dim3(128)>>>(P_, k_, (unsigned*)dq_);
        attn_av_mma_k<true ><<<dim3(4, BHN), dim3(128)>>>(P_, q_, dk_);
        mma_gemm_k<false, false, true, false, true><<<gridHid, blk512, SMEM_GEMM_BYTES>>>(
            g_, hopt_, nullptr, (float*)h_, MROWS, HIDN, TKN);
        mma_gemm_k<true, false, false, true, false><<<grid768, blk512, SMEM_GEMM_BYTES>>>(
            (unsigned*)dq_, wqt_, nullptr, t_, MROWS, TKN, TKN);
        mma_gemm_k<true, false, false, true, false><<<grid768, blk512, SMEM_GEMM_BYTES>>>(
            dk_, wkt_, nullptr, t_, MROWS, TKN, TKN);
        mma_gemm_k<true, false, false, true, false><<<grid768, blk512, SMEM_GEMM_BYTES>>>(
            h_, hopt_, nullptr, t_, MROWS, TKN, HIDN);
    }

    ln_kernel<<<MROWS, blk>>>(t_, dec_w, dec_b, g_, 0);
    mma_gemm_k<false, true, false, false, false><<<grid768, blk512, SMEM_GEMM_BYTES>>>(
        g_, dect_, b_dec, dq_, MROWS, TKN, TKN);
    copy_out_k<<<(BB * NTOK * TKN + 255) / 256, blk>>>(dq_, out);
}

// round 6
// speedup vs baseline: 3.3321x; 1.0392x over previous
#include <cuda_runtime.h>
#include <math.h>

// ---------------- problem constants ----------------
#define BB    32
#define NTOK  196
#define NP1   197
#define TKN   768
#define HH    12
#define ZZ    64
#define HIDN  3072
#define MROWS (BB*NP1)    // 6304
#define MENC  (BB*NTOK)   // 6272
#define BHN   (BB*HH)     // 384
#define KSTEPS 12
#define BETA_S 0.125f
#define EPS_LN 1e-5f
#define QKW   1536
#define BIGK  4608

// ---------------- scratch (device globals; no allocation) ----------------
__device__ float    g_t    [MROWS*TKN];     // fp32 state
__device__ unsigned g_g    [MROWS*TKN];     // tf32 bits (LN output)
__device__ unsigned g_qk   [MROWS*QKW];     // tf32 bits: cols 0..767 q, 768..1535 k
__device__ unsigned g_dqdkh[MROWS*BIGK];    // tf32 bits: dq | dk | relu(h)
__device__ float    g_P    [BHN*NP1*NP1];   // tf32 bits (post-softmax)
__device__ float    g_tmp  [MROWS*TKN];     // fp32 temp (encode/decode out)
__device__ unsigned g_wstack[BIGK*TKN];     // tf32: wq | wk | w_hop rows
__device__ unsigned g_enct [TKN*TKN];
__device__ unsigned g_dect [TKN*TKN];
__device__ unsigned g_xt   [MENC*TKN];

__device__ __forceinline__ unsigned f2tf(float f) {
    unsigned u;
    asm("cvt.rna.tf32.f32 %0, %1;" : "=r"(u) : "f"(f));
    return u;
}

__device__ __forceinline__ void mma8(float c[4], const unsigned a[4], const unsigned b[2]) {
    asm volatile(
        "mma.sync.aligned.m16n8k8.row.col.f32.tf32.tf32.f32 "
        "{%0,%1,%2,%3}, {%4,%5,%6,%7}, {%8,%9}, {%0,%1,%2,%3};\n"
        : "+f"(c[0]), "+f"(c[1]), "+f"(c[2]), "+f"(c[3])
        : "r"(a[0]), "r"(a[1]), "r"(a[2]), "r"(a[3]), "r"(b[0]), "r"(b[1]));
}

__global__ void cvt_tf32_k(const float* __restrict__ in, unsigned* __restrict__ out, int n)
{
    int i = blockIdx.x * 256 + threadIdx.x;
    if (i < n) out[i] = f2tf(in[i]);
}

// ================== tf32 tensor-core GEMM (cp.async, BK=32, 3-stage) ==================
#define STAGES 3
#define BM 256
#define BN 128
#define BK 32
#define AS_STRIDE 36
#define BT_STRIDE 36
#define BNN_STRIDE 136
#define A_STG (BM*AS_STRIDE)
#define B_STG 4608
#define SMEM_GEMM_BYTES (STAGES*(A_STG+B_STG)*4)   // 165888

__device__ __forceinline__ void cp16(unsigned dst, const void* src, int sz) {
    asm volatile("cp.async.cg.shared.global [%0], [%1], 16, %2;\n"
                 :: "r"(dst), "l"(src), "r"(sz));
}
__device__ __forceinline__ void cp_commit() { asm volatile("cp.async.commit_group;\n"); }
__device__ __forceinline__ void cp_wait1()  { asm volatile("cp.async.wait_group 1;\n"); }

template<bool NN>
__device__ __forceinline__ void load_stage(
    const unsigned* __restrict__ A, const unsigned* __restrict__ B,
    int M, int N, int K, int m0, int n0, int kt, int tid,
    unsigned sA, unsigned sB)
{
#pragma unroll
    for (int s = 0; s < 4; s++) {
        int id = tid + s * 512;
        int r = id >> 3, c = (id & 7) << 2;
        unsigned dst = sA + (unsigned)(r * AS_STRIDE + c) * 4u;
        bool ok = (m0 + r < M);
        const unsigned* src = ok ? (A + (size_t)(m0 + r) * K + kt + c) : A;
        cp16(dst, src, ok ? 16 : 0);
    }
#pragma unroll
    for (int s = 0; s < 2; s++) {
        int id = tid + s * 512;
        if (!NN) {
            int r = id >> 3, c = (id & 7) << 2;
            unsigned dst = sB + (unsigned)(r * BT_STRIDE + c) * 4u;
            cp16(dst, B + (size_t)(n0 + r) * K + kt + c, 16);
        } else {
            int r = id >> 5, c = (id & 31) << 2;
            unsigned dst = sB + (unsigned)(r * BNN_STRIDE + c) * 4u;
            cp16(dst, B + (size_t)(kt + r) * N + n0 + c, 16);
        }
    }
}

template<bool NN, bool BIAS, bool RELU, bool ACC, bool OTF>
__global__ void __launch_bounds__(512, 1) mma_gemm_k(
    const unsigned* __restrict__ A, const unsigned* __restrict__ B,
    const float* __restrict__ bias, float* __restrict__ C,
    int M, int N, int K, int ldc)
{
    extern __shared__ unsigned sm[];
    const int tid = threadIdx.x;
    const int m0 = blockIdx.y * BM, n0 = blockIdx.x * BN;
    const int lane = tid & 31, wid = tid >> 5;
    const int wm = (wid & 3) * 64, wn = (wid >> 2) * 32;
    const int g = lane >> 2, tig = lane & 3;

    unsigned smem_u = (unsigned)__cvta_generic_to_shared(sm);
    unsigned sB_base = smem_u + (unsigned)(STAGES * A_STG) * 4u;

    float acc[4][4][4];
#pragma unroll
    for (int mi = 0; mi < 4; mi++)
#pragma unroll
        for (int ni = 0; ni < 4; ni++)
#pragma unroll
            for (int v = 0; v < 4; v++) acc[mi][ni][v] = 0.f;

    const int niter = K >> 5;

#pragma unroll
    for (int p = 0; p < STAGES - 1; p++) {
        load_stage<NN>(A, B, M, N, K, m0, n0, p * BK, tid,
                       smem_u + (unsigned)(p * A_STG) * 4u,
                       sB_base + (unsigned)(p * B_STG) * 4u);
        cp_commit();
    }

    int stc = 0;
    for (int it = 0; it < niter; it++) {
        cp_wait1();
        __syncthreads();

        int pf = it + STAGES - 1;
        if (pf < niter) {
            int st = pf % STAGES;
            load_stage<NN>(A, B, M, N, K, m0, n0, pf * BK, tid,
                           smem_u + (unsigned)(st * A_STG) * 4u,
                           sB_base + (unsigned)(st * B_STG) * 4u);
        }
        cp_commit();

        const unsigned* Ab = sm + stc * A_STG;
        const unsigned* Bb = sm + STAGES * A_STG + stc * B_STG;
        stc = (stc + 1 == STAGES) ? 0 : stc + 1;
#pragma unroll
        for (int ks = 0; ks < 4; ks++) {
            unsigned af[4][4], bf[4][2];
#pragma unroll
            for (int mi = 0; mi < 4; mi++) {
                const unsigned* p0 = Ab + (wm + mi * 16 + g) * AS_STRIDE + ks * 8 + tig;
                af[mi][0] = p0[0];
                af[mi][1] = p0[8 * AS_STRIDE];
                af[mi][2] = p0[4];
                af[mi][3] = p0[8 * AS_STRIDE + 4];
            }
#pragma unroll
            for (int ni = 0; ni < 4; ni++) {
                if (!NN) {
                    const unsigned* p = Bb + (wn + ni * 8 + g) * BT_STRIDE + ks * 8 + tig;
                    bf[ni][0] = p[0];
                    bf[ni][1] = p[4];
                } else {
                    const unsigned* p = Bb + (ks * 8 + tig) * BNN_STRIDE + wn + ni * 8 + g;
                    bf[ni][0] = p[0];
                    bf[ni][1] = p[4 * BNN_STRIDE];
                }
            }
#pragma unroll
            for (int mi = 0; mi < 4; mi++)
#pragma unroll
                for (int ni = 0; ni < 4; ni++)
                    mma8(acc[mi][ni], af[mi], bf[ni]);
        }
    }

#pragma unroll
    for (int mi = 0; mi < 4; mi++) {
#pragma unroll
        for (int half = 0; half < 2; half++) {
            int row = m0 + wm + mi * 16 + g + half * 8;
            if (row < M) {
                float* crow = C + (size_t)row * ldc;
#pragma unroll
                for (int ni = 0; ni < 4; ni++) {
                    int col = n0 + wn + ni * 8 + tig * 2;
                    float v0 = acc[mi][ni][half * 2 + 0];
                    float v1 = acc[mi][ni][half * 2 + 1];
                    if (BIAS) { v0 += bias[col]; v1 += bias[col + 1]; }
                    if (RELU) { v0 = fmaxf(v0, 0.f); v1 = fmaxf(v1, 0.f); }
                    if (ACC)  { v0 += crow[col]; v1 += crow[col + 1]; }
                    if (OTF)  { crow[col] = __uint_as_float(f2tf(v0));
                                crow[col + 1] = __uint_as_float(f2tf(v1)); }
                    else      { crow[col] = v0; crow[col + 1] = v1; }
                }
            }
        }
    }
}

// ---------------- LayerNorm (writes tf32 bits) ----------------
__device__ __forceinline__ float block_sum_256(float v, float* red)
{
    int lane = threadIdx.x & 31, w = threadIdx.x >> 5;
#pragma unroll
    for (int o = 16; o; o >>= 1) v += __shfl_xor_sync(0xffffffffu, v, o);
    if (lane == 0) red[w] = v;
    __syncthreads();
    if (w == 0) {
        float r = (lane < 8) ? red[lane] : 0.f;
#pragma unroll
        for (int o = 4; o; o >>= 1) r += __shfl_xor_sync(0xffffffffu, r, o);
        if (lane == 0) red[0] = r;
    }
    __syncthreads();
    float out = red[0];
    __syncthreads();
    return out;
}

__global__ void __launch_bounds__(256) ln_kernel(
    const float* __restrict__ X, const float* __restrict__ w,
    const float* __restrict__ bvec, unsigned* __restrict__ Y, int scalar_w)
{
    __shared__ float red[32];
    int row = blockIdx.x;
    const float* x = X + (size_t)row * TKN;
    unsigned* y = Y + (size_t)row * TKN;
    int tid = threadIdx.x;
    float v[3];
    float s = 0.f, ss = 0.f;
#pragma unroll
    for (int i = 0; i < 3; i++) {
        float t = x[tid + i * 256];
        v[i] = t; s += t; ss += t * t;
    }
    float sum  = block_sum_256(s, red);
    float sum2 = block_sum_256(ss, red);
    float mu = sum * (1.f / TKN);
    float var = sum2 * (1.f / TKN) - mu * mu;
    float r = rsqrtf(var + EPS_LN);
#pragma unroll
    for (int i = 0; i < 3; i++) {
        int c = tid + i * 256;
        float gv = (v[i] - mu) * r;
        float wv = scalar_w ? w[0] : w[c];
        y[c] = f2tf(gv * wv + bvec[c]);
    }
}

// ---------------- assemble t = [cls ; enc] + pos ----------------
__global__ void assemble_t_k(const float* __restrict__ enc,
                             const float* __restrict__ cls,
                             const float* __restrict__ pos)
{
    int idx = blockIdx.x * 256 + threadIdx.x;
    if (idx >= MROWS * TKN) return;
    int d = idx % TKN;
    int row = idx / TKN;
    int b = row / NP1, n = row % NP1;
    float v;
    if (n == 0) v = cls[d];
    else        v = enc[((size_t)(b * NTOK + n - 1)) * TKN + d];
    g_t[idx] = v + pos[n * TKN + d];
}

// ---------------- fused scores + softmax ----------------
// grid (4 qtiles, BHN), 256 threads.
// smem: Q 64x68 u32 + K 64x68 u32 + Sc 64x264 f32 (stride 264 covers cols 0..255)
#define SC_STRIDE 264
#define SS_SMEM ((2*64*68 + 64*SC_STRIDE) * 4)   // 102400
__global__ void __launch_bounds__(256) attn_score_softmax_k(
    const unsigned* __restrict__ QK, float* __restrict__ P)
{
    extern __shared__ unsigned ssm[];
    unsigned* Qs = ssm;
    unsigned* Ks = ssm + 64 * 68;
    float*    Sc = (float*)(ssm + 2 * 64 * 68);

    int bh = blockIdx.y, b = bh / HH, h = bh % HH;
    int q0 = blockIdx.x * 64;
    const unsigned* Qb = QK + (size_t)b * NP1 * QKW + h * ZZ;
    const unsigned* Kb = Qb + TKN;
    int tid = threadIdx.x;
    int lane = tid & 31, wid = tid >> 5;
    int wm = (wid & 3) * 16, wn = (wid >> 2) * 32;
    int g = lane >> 2, tig = lane & 3;

#pragma unroll
    for (int s = 0; s < 4; s++) {
        int id = tid + s * 256;
        int r = id >> 4, c4 = (id & 15) << 2;
        uint4 qv = (q0 + r < NP1) ? *(const uint4*)(Qb + (size_t)(q0 + r) * QKW + c4)
                                  : make_uint4(0u, 0u, 0u, 0u);
        *(uint4*)&Qs[r * 68 + c4] = qv;
    }

    for (int kt = 0; kt < 4; kt++) {
        int k0 = kt * 64;
        __syncthreads();
#pragma unroll
        for (int s = 0; s < 4; s++) {
            int id = tid + s * 256;
            int r = id >> 4, c4 = (id & 15) << 2;
            uint4 kv = (k0 + r < NP1) ? *(const uint4*)(Kb + (size_t)(k0 + r) * QKW + c4)
                                      : make_uint4(0u, 0u, 0u, 0u);
            *(uint4*)&Ks[r * 68 + c4] = kv;
        }
        __syncthreads();

        float acc[4][4];
#pragma unroll
        for (int ni = 0; ni < 4; ni++)
#pragma unroll
            for (int v = 0; v < 4; v++) acc[ni][v] = 0.f;
#pragma unroll
        for (int ks = 0; ks < 8; ks++) {
            unsigned af[4], bf[4][2];
            const unsigned* pa = Qs + (wm + g) * 68 + ks * 8 + tig;
            af[0] = pa[0]; af[1] = pa[8 * 68]; af[2] = pa[4]; af[3] = pa[8 * 68 + 4];
#pragma unroll
            for (int ni = 0; ni < 4; ni++) {
                const unsigned* pb = Ks + (wn + ni * 8 + g) * 68 + ks * 8 + tig;
                bf[ni][0] = pb[0]; bf[ni][1] = pb[4];
            }
#pragma unroll
            for (int ni = 0; ni < 4; ni++)
                mma8(acc[ni], af, bf[ni]);
        }
#pragma unroll
        for (int half = 0; half < 2; half++) {
            int row = wm + g + half * 8;
#pragma unroll
            for (int ni = 0; ni < 4; ni++) {
                int col = k0 + wn + ni * 8 + tig * 2;
                Sc[row * SC_STRIDE + col]     = acc[ni][half * 2 + 0];
                Sc[row * SC_STRIDE + col + 1] = acc[ni][half * 2 + 1];
            }
        }
    }
    __syncthreads();

    // softmax: warp wid handles rows wid*8 .. wid*8+7
    float* Pp = P + (size_t)bh * NP1 * NP1;
#pragma unroll
    for (int rr = 0; rr < 8; rr++) {
        int row = wid * 8 + rr;
        int grow = q0 + row;
        if (grow >= NP1) continue;
        float vals[7];
        float m = -1e30f;
#pragma unroll
        for (int i = 0; i < 7; i++) {
            int c = lane + i * 32;
            float v = (c < NP1) ? BETA_S * Sc[row * SC_STRIDE + c] : -1e30f;
            vals[i] = v;
            m = fmaxf(m, v);
        }
#pragma unroll
        for (int o = 16; o; o >>= 1) m = fmaxf(m, __shfl_xor_sync(0xffffffffu, m, o));
        float s = 0.f;
#pragma unroll
        for (int i = 0; i < 7; i++) {
            int c = lane + i * 32;
            float e = (c < NP1) ? expf(vals[i] - m) : 0.f;
            vals[i] = e; s += e;
        }
#pragma unroll
        for (int o = 16; o; o >>= 1) s += __shfl_xor_sync(0xffffffffu, s, o);
        float inv = 1.f / s;
        float* prow = Pp + (size_t)grow * NP1;
#pragma unroll
        for (int i = 0; i < 7; i++) {
            int c = lane + i * 32;
            if (c < NP1) prow[c] = __uint_as_float(f2tf(vals[i] * inv));
        }
    }
}

// ---------------- attention PV via mma ----------------
// TRANSP=false: dq = P @ K ; TRANSP=true: dk = P^T @ Q.  Writes tf32 into dqdkh.
template<bool TRANSP>
__global__ void __launch_bounds__(128) attn_av_mma_k(
    const float* __restrict__ Pb, const unsigned* __restrict__ QK,
    unsigned* __restrict__ OutB, int v_off, int o_off)
{
    __shared__ unsigned Ps[64 * 36];
    __shared__ unsigned Vs[32 * 72];
    int bh = blockIdx.y, b = bh / HH, h = bh % HH;
    const float* Pp = Pb + (size_t)bh * NP1 * NP1;
    const unsigned* Vb = QK + (size_t)b * NP1 * QKW + v_off + h * ZZ;
    unsigned* Ob = OutB + (size_t)b * NP1 * BIGK + o_off + h * ZZ;
    int m0 = blockIdx.x * 64;
    int tid = threadIdx.x, lane = tid & 31, wid = tid >> 5;
    int g = lane >> 2, tig = lane & 3, wm = wid * 16;
    float acc[8][4];
#pragma unroll
    for (int ni = 0; ni < 8; ni++)
#pragma unroll
        for (int v = 0; v < 4; v++) acc[ni][v] = 0.f;

    for (int kb = 0; kb < NP1; kb += 32) {
        __syncthreads();
#pragma unroll
        for (int s = 0; s < 16; s++) {
            int id = tid + s * 128;
            int r, kk;
            if (!TRANSP) { r = id >> 5; kk = id & 31; }
            else         { r = id & 63; kk = id >> 6; }
            float v = 0.f;
            int mg = m0 + r, kg = kb + kk;
            if (mg < NP1 && kg < NP1)
                v = TRANSP ? Pp[(size_t)kg * NP1 + mg] : Pp[(size_t)mg * NP1 + kg];
            Ps[r * 36 + kk] = __float_as_uint(v);
        }
#pragma unroll
        for (int s = 0; s < 4; s++) {
            int id = tid + s * 128;
            int r = id >> 4, c4 = (id & 15) << 2;
            uint4 v = (kb + r < NP1) ? *(const uint4*)(Vb + (size_t)(kb + r) * QKW + c4)
                                     : make_uint4(0u, 0u, 0u, 0u);
            *(uint4*)&Vs[r * 72 + c4] = v;
        }
        __syncthreads();
#pragma unroll
        for (int ks = 0; ks < 4; ks++) {
            unsigned af[4], bf[8][2];
            const unsigned* pa = Ps + (wm + g) * 36 + ks * 8 + tig;
            af[0] = pa[0]; af[1] = pa[8 * 36]; af[2] = pa[4]; af[3] = pa[8 * 36 + 4];
#pragma unroll
            for (int ni = 0; ni < 8; ni++) {
                const unsigned* pb = Vs + (ks * 8 + tig) * 72 + ni * 8 + g;
                bf[ni][0] = pb[0]; bf[ni][1] = pb[4 * 72];
            }
#pragma unroll
            for (int ni = 0; ni < 8; ni++)
                mma8(acc[ni], af, bf[ni]);
        }
    }
#pragma unroll
    for (int half = 0; half < 2; half++) {
        int row = m0 + wm + g + half * 8;
        if (row < NP1) {
            unsigned* orow = Ob + (size_t)row * BIGK;
#pragma unroll
            for (int ni = 0; ni < 8; ni++) {
                int col = ni * 8 + tig * 2;
                orow[col]     = f2tf(acc[ni][half * 2]);
                orow[col + 1] = f2tf(acc[ni][half * 2 + 1]);
            }
        }
    }
}

// ---------------- final copy (drop cls row) ----------------
__global__ void copy_out_k(const float* __restrict__ Y, float* __restrict__ out)
{
    int idx = blockIdx.x * 256 + threadIdx.x;
    if (idx >= BB * NTOK * TKN) return;
    int d = idx % TKN;
    int r = idx / TKN;
    int b = r / NTOK, j = r % NTOK;
    out[idx] = Y[((size_t)(b * NP1 + j + 1)) * TKN + d];
}

// ---------------- driver ----------------
extern "C" void kernel_launch(void* const* d_in, const int* in_sizes, int n_in,
                              void* d_out, int out_size)
{
    const float* x      = (const float*)d_in[0];
    const float* w_enc  = (const float*)d_in[1];
    const float* b_enc  = (const float*)d_in[2];
    const float* cls    = (const float*)d_in[3];
    const float* pos    = (const float*)d_in[4];
    const float* eln_g  = (const float*)d_in[5];
    const float* eln_b  = (const float*)d_in[6];
    const float* wq     = (const float*)d_in[7];
    const float* wk     = (const float*)d_in[8];
    const float* w_hop  = (const float*)d_in[9];
    const float* dec_w  = (const float*)d_in[10];
    const float* dec_b  = (const float*)d_in[11];
    const float* w_dec  = (const float*)d_in[12];
    const float* b_dec  = (const float*)d_in[13];
    float* out = (float*)d_out;

    float *t_, *P_, *tmp_;
    unsigned *g_, *qk_, *dqdkh_, *wstack_, *enct_, *dect_, *xt_;
    cudaGetSymbolAddress((void**)&t_,     g_t);
    cudaGetSymbolAddress((void**)&g_,     g_g);
    cudaGetSymbolAddress((void**)&qk_,    g_qk);
    cudaGetSymbolAddress((void**)&dqdkh_, g_dqdkh);
    cudaGetSymbolAddress((void**)&P_,     g_P);
    cudaGetSymbolAddress((void**)&tmp_,   g_tmp);
    cudaGetSymbolAddress((void**)&wstack_,g_wstack);
    cudaGetSymbolAddress((void**)&enct_,  g_enct);
    cudaGetSymbolAddress((void**)&dect_,  g_dect);
    cudaGetSymbolAddress((void**)&xt_,    g_xt);

    cudaFuncSetAttribute((const void*)mma_gemm_k<false, true,  false, false, false>,
                         cudaFuncAttributeMaxDynamicSharedMemorySize, SMEM_GEMM_BYTES);
    cudaFuncSetAttribute((const void*)mma_gemm_k<false, false, false, false, true>,
                         cudaFuncAttributeMaxDynamicSharedMemorySize, SMEM_GEMM_BYTES);
    cudaFuncSetAttribute((const void*)mma_gemm_k<false, false, true,  false, true>,
                         cudaFuncAttributeMaxDynamicSharedMemorySize, SMEM_GEMM_BYTES);
    cudaFuncSetAttribute((const void*)mma_gemm_k<true,  false, false, true,  false>,
                         cudaFuncAttributeMaxDynamicSharedMemorySize, SMEM_GEMM_BYTES);
    cudaFuncSetAttribute((const void*)attn_score_softmax_k,
                         cudaFuncAttributeMaxDynamicSharedMemorySize, SS_SMEM);

    const dim3 blk512(512);
    const dim3 blk(256);
    const int  mtiles = (MROWS + BM - 1) / BM;   // 25
    const dim3 gridProj(QKW / BN, mtiles);       // (12, 25)
    const dim3 gridHid(HIDN / BN, mtiles);       // (24, 25)
    const dim3 gridMega(TKN / BN, mtiles);       // (6, 25)
    const dim3 gridEnc(TKN / BN, (MENC + BM - 1) / BM);

    // one-time tf32 conversions (wstack = [wq | wk | w_hop])
    cvt_tf32_k<<<(TKN*TKN + 255) / 256, blk>>>(wq,    wstack_,              TKN*TKN);
    cvt_tf32_k<<<(TKN*TKN + 255) / 256, blk>>>(wk,    wstack_ + TKN*TKN,    TKN*TKN);
    cvt_tf32_k<<<(HIDN*TKN + 255) / 256, blk>>>(w_hop, wstack_ + 2*TKN*TKN, HIDN*TKN);
    cvt_tf32_k<<<(TKN*TKN + 255) / 256, blk>>>(w_enc, enct_, TKN*TKN);
    cvt_tf32_k<<<(TKN*TKN + 255) / 256, blk>>>(w_dec, dect_, TKN*TKN);
    cvt_tf32_k<<<(MENC*TKN + 255) / 256, blk>>>(x,     xt_,   MENC*TKN);

    // encode + assemble
    mma_gemm_k<false, true, false, false, false><<<gridEnc, blk512, SMEM_GEMM_BYTES>>>(
        xt_, enct_, b_enc, tmp_, MENC, TKN, TKN, TKN);
    assemble_t_k<<<(MROWS * TKN + 255) / 256, blk>>>(tmp_, cls, pos);

    for (int s = 0; s < KSTEPS; s++) {
        ln_kernel<<<MROWS, blk>>>(t_, eln_g, eln_b, g_, 1);
        // fused q|k projection
        mma_gemm_k<false, false, false, false, true><<<gridProj, blk512, SMEM_GEMM_BYTES>>>(
            g_, wstack_, nullptr, (float*)qk_, MROWS, QKW, TKN, QKW);
        attn_score_softmax_k<<<dim3(4, BHN), blk, SS_SMEM>>>(qk_, P_);
        attn_av_mma_k<false><<<dim3(4, BHN), dim3(128)>>>(P_, qk_, dqdkh_, TKN, 0);
        attn_av_mma_k<true ><<<dim3(4, BHN), dim3(128)>>>(P_, qk_, dqdkh_, 0, TKN);
        // hopfield: relu(g @ w_hop^T) -> dqdkh cols 1536..4607
        mma_gemm_k<false, false, true, false, true><<<gridHid, blk512, SMEM_GEMM_BYTES>>>(
            g_, wstack_ + 2*TKN*TKN, nullptr, (float*)(dqdkh_ + QKW), MROWS, HIDN, TKN, BIGK);
        // mega accumulate: t += [dq|dk|relu(h)] @ [wq;wk;w_hop]
        mma_gemm_k<true, false, false, true, false><<<gridMega, blk512, SMEM_GEMM_BYTES>>>(
            dqdkh_, wstack_, nullptr, t_, MROWS, TKN, BIGK, TKN);
    }

    ln_kernel<<<MROWS, blk>>>(t_, dec_w, dec_b, g_, 0);
    mma_gemm_k<false, true, false, false, false><<<gridMega, blk512, SMEM_GEMM_BYTES>>>(
        g_, dect_, b_dec, tmp_, MROWS, TKN, TKN, TKN);
    copy_out_k<<<(BB * NTOK * TKN + 255) / 256, blk>>>(tmp_, out);
}

// round 7
// speedup vs baseline: 3.4810x; 1.0447x over previous
#include <cuda_runtime.h>
#include <math.h>

// ---------------- problem constants ----------------
#define BB    32
#define NTOK  196
#define NP1   197
#define TKN   768
#define HH    12
#define ZZ    64
#define HIDN  3072
#define MROWS (BB*NP1)    // 6304
#define MENC  (BB*NTOK)   // 6272
#define BHN   (BB*HH)     // 384
#define KSTEPS 12
#define BETA_S 0.125f
#define EPS_LN 1e-5f
#define QKW   1536
#define BIGK  4608

// ---------------- scratch (device globals; no allocation) ----------------
__device__ float    g_t    [MROWS*TKN];
__device__ unsigned g_g    [MROWS*TKN];
__device__ unsigned g_qk   [MROWS*QKW];
__device__ unsigned g_dqdkh[MROWS*BIGK];
__device__ float    g_P    [BHN*NP1*NP1];
__device__ float    g_tmp  [MROWS*TKN];
__device__ unsigned g_wstack[BIGK*TKN];
__device__ unsigned g_enct [TKN*TKN];
__device__ unsigned g_dect [TKN*TKN];
__device__ unsigned g_xt   [MENC*TKN];

__device__ __forceinline__ unsigned f2tf(float f) {
    unsigned u;
    asm("cvt.rna.tf32.f32 %0, %1;" : "=r"(u) : "f"(f));
    return u;
}

__device__ __forceinline__ void mma8(float c[4], const unsigned a[4], const unsigned b[2]) {
    asm volatile(
        "mma.sync.aligned.m16n8k8.row.col.f32.tf32.tf32.f32 "
        "{%0,%1,%2,%3}, {%4,%5,%6,%7}, {%8,%9}, {%0,%1,%2,%3};\n"
        : "+f"(c[0]), "+f"(c[1]), "+f"(c[2]), "+f"(c[3])
        : "r"(a[0]), "r"(a[1]), "r"(a[2]), "r"(a[3]), "r"(b[0]), "r"(b[1]));
}

__global__ void cvt_tf32_k(const float* __restrict__ in, unsigned* __restrict__ out, int n)
{
    int i = blockIdx.x * 256 + threadIdx.x;
    if (i < n) out[i] = f2tf(in[i]);
}

// ============ tf32 GEMM: BM=256 BN=128 BK=32, 256 thr (8 warps 4x2), warp 64x64 ============
#define STAGES 3
#define BM 256
#define BN 128
#define BK 32
#define AS_STRIDE 36
#define BT_STRIDE 36
#define BNN_STRIDE 136
#define A_STG (BM*AS_STRIDE)
#define B_STG 4608
#define SMEM_GEMM_BYTES (STAGES*(A_STG+B_STG)*4)   // 165888

__device__ __forceinline__ void cp16(unsigned dst, const void* src, int sz) {
    asm volatile("cp.async.cg.shared.global [%0], [%1], 16, %2;\n"
                 :: "r"(dst), "l"(src), "r"(sz));
}
__device__ __forceinline__ void cp_commit() { asm volatile("cp.async.commit_group;\n"); }
__device__ __forceinline__ void cp_wait1()  { asm volatile("cp.async.wait_group 1;\n"); }

template<bool NN>
__device__ __forceinline__ void load_stage(
    const unsigned* __restrict__ A, const unsigned* __restrict__ B,
    int M, int N, int K, int m0, int n0, int kt, int tid,
    unsigned sA, unsigned sB)
{
#pragma unroll
    for (int s = 0; s < 8; s++) {
        int id = tid + s * 256;
        int r = id >> 3, c = (id & 7) << 2;
        unsigned dst = sA + (unsigned)(r * AS_STRIDE + c) * 4u;
        bool ok = (m0 + r < M);
        const unsigned* src = ok ? (A + (size_t)(m0 + r) * K + kt + c) : A;
        cp16(dst, src, ok ? 16 : 0);
    }
#pragma unroll
    for (int s = 0; s < 4; s++) {
        int id = tid + s * 256;
        if (!NN) {
            int r = id >> 3, c = (id & 7) << 2;
            unsigned dst = sB + (unsigned)(r * BT_STRIDE + c) * 4u;
            cp16(dst, B + (size_t)(n0 + r) * K + kt + c, 16);
        } else {
            int r = id >> 5, c = (id & 31) << 2;
            unsigned dst = sB + (unsigned)(r * BNN_STRIDE + c) * 4u;
            cp16(dst, B + (size_t)(kt + r) * N + n0 + c, 16);
        }
    }
}

template<bool NN, bool BIAS, bool RELU, bool ACC, bool OTF>
__global__ void __launch_bounds__(256, 1) mma_gemm_k(
    const unsigned* __restrict__ A, const unsigned* __restrict__ B,
    const float* __restrict__ bias, float* __restrict__ C,
    int M, int N, int K, int ldc)
{
    extern __shared__ unsigned sm[];
    const int tid = threadIdx.x;
    const int m0 = blockIdx.y * BM, n0 = blockIdx.x * BN;
    const int lane = tid & 31, wid = tid >> 5;
    const int wm = (wid & 3) * 64, wn = (wid >> 2) * 64;
    const int g = lane >> 2, tig = lane & 3;

    unsigned smem_u = (unsigned)__cvta_generic_to_shared(sm);
    unsigned sB_base = smem_u + (unsigned)(STAGES * A_STG) * 4u;

    float acc[4][8][4];
#pragma unroll
    for (int mi = 0; mi < 4; mi++)
#pragma unroll
        for (int ni = 0; ni < 8; ni++)
#pragma unroll
            for (int v = 0; v < 4; v++) acc[mi][ni][v] = 0.f;

    const int niter = K >> 5;

#pragma unroll
    for (int p = 0; p < STAGES - 1; p++) {
        load_stage<NN>(A, B, M, N, K, m0, n0, p * BK, tid,
                       smem_u + (unsigned)(p * A_STG) * 4u,
                       sB_base + (unsigned)(p * B_STG) * 4u);
        cp_commit();
    }

    int stc = 0;
    for (int it = 0; it < niter; it++) {
        cp_wait1();
        __syncthreads();

        int pf = it + STAGES - 1;
        if (pf < niter) {
            int st = pf % STAGES;
            load_stage<NN>(A, B, M, N, K, m0, n0, pf * BK, tid,
                           smem_u + (unsigned)(st * A_STG) * 4u,
                           sB_base + (unsigned)(st * B_STG) * 4u);
        }
        cp_commit();

        const unsigned* Ab = sm + stc * A_STG;
        const unsigned* Bb = sm + STAGES * A_STG + stc * B_STG;
        stc = (stc + 1 == STAGES) ? 0 : stc + 1;
#pragma unroll
        for (int ks = 0; ks < 4; ks++) {
            unsigned af[4][4], bf[8][2];
#pragma unroll
            for (int mi = 0; mi < 4; mi++) {
                const unsigned* p0 = Ab + (wm + mi * 16 + g) * AS_STRIDE + ks * 8 + tig;
                af[mi][0] = p0[0];
                af[mi][1] = p0[8 * AS_STRIDE];
                af[mi][2] = p0[4];
                af[mi][3] = p0[8 * AS_STRIDE + 4];
            }
#pragma unroll
            for (int ni = 0; ni < 8; ni++) {
                if (!NN) {
                    const unsigned* p = Bb + (wn + ni * 8 + g) * BT_STRIDE + ks * 8 + tig;
                    bf[ni][0] = p[0];
                    bf[ni][1] = p[4];
                } else {
                    const unsigned* p = Bb + (ks * 8 + tig) * BNN_STRIDE + wn + ni * 8 + g;
                    bf[ni][0] = p[0];
                    bf[ni][1] = p[4 * BNN_STRIDE];
                }
            }
#pragma unroll
            for (int mi = 0; mi < 4; mi++)
#pragma unroll
                for (int ni = 0; ni < 8; ni++)
                    mma8(acc[mi][ni], af[mi], bf[ni]);
        }
    }

#pragma unroll
    for (int mi = 0; mi < 4; mi++) {
#pragma unroll
        for (int half = 0; half < 2; half++) {
            int row = m0 + wm + mi * 16 + g + half * 8;
            if (row < M) {
                float* crow = C + (size_t)row * ldc;
#pragma unroll
                for (int ni = 0; ni < 8; ni++) {
                    int col = n0 + wn + ni * 8 + tig * 2;
                    float v0 = acc[mi][ni][half * 2 + 0];
                    float v1 = acc[mi][ni][half * 2 + 1];
                    if (BIAS) { v0 += bias[col]; v1 += bias[col + 1]; }
                    if (RELU) { v0 = fmaxf(v0, 0.f); v1 = fmaxf(v1, 0.f); }
                    if (ACC)  { v0 += crow[col]; v1 += crow[col + 1]; }
                    if (OTF)  { crow[col] = __uint_as_float(f2tf(v0));
                                crow[col + 1] = __uint_as_float(f2tf(v1)); }
                    else      { crow[col] = v0; crow[col + 1] = v1; }
                }
            }
        }
    }
}

// ---------------- LayerNorm (writes tf32 bits) ----------------
__device__ __forceinline__ float block_sum_256(float v, float* red)
{
    int lane = threadIdx.x & 31, w = threadIdx.x >> 5;
#pragma unroll
    for (int o = 16; o; o >>= 1) v += __shfl_xor_sync(0xffffffffu, v, o);
    if (lane == 0) red[w] = v;
    __syncthreads();
    if (w == 0) {
        float r = (lane < 8) ? red[lane] : 0.f;
#pragma unroll
        for (int o = 4; o; o >>= 1) r += __shfl_xor_sync(0xffffffffu, r, o);
        if (lane == 0) red[0] = r;
    }
    __syncthreads();
    float out = red[0];
    __syncthreads();
    return out;
}

__global__ void __launch_bounds__(256) ln_kernel(
    const float* __restrict__ X, const float* __restrict__ w,
    const float* __restrict__ bvec, unsigned* __restrict__ Y, int scalar_w)
{
    __shared__ float red[32];
    int row = blockIdx.x;
    const float* x = X + (size_t)row * TKN;
    unsigned* y = Y + (size_t)row * TKN;
    int tid = threadIdx.x;
    float v[3];
    float s = 0.f, ss = 0.f;
#pragma unroll
    for (int i = 0; i < 3; i++) {
        float t = x[tid + i * 256];
        v[i] = t; s += t; ss += t * t;
    }
    float sum  = block_sum_256(s, red);
    float sum2 = block_sum_256(ss, red);
    float mu = sum * (1.f / TKN);
    float var = sum2 * (1.f / TKN) - mu * mu;
    float r = rsqrtf(var + EPS_LN);
#pragma unroll
    for (int i = 0; i < 3; i++) {
        int c = tid + i * 256;
        float gv = (v[i] - mu) * r;
        float wv = scalar_w ? w[0] : w[c];
        y[c] = f2tf(gv * wv + bvec[c]);
    }
}

// ---------------- assemble t = [cls ; enc] + pos ----------------
__global__ void assemble_t_k(const float* __restrict__ enc,
                             const float* __restrict__ cls,
                             const float* __restrict__ pos)
{
    int idx = blockIdx.x * 256 + threadIdx.x;
    if (idx >= MROWS * TKN) return;
    int d = idx % TKN;
    int row = idx / TKN;
    int b = row / NP1, n = row % NP1;
    float v;
    if (n == 0) v = cls[d];
    else        v = enc[((size_t)(b * NTOK + n - 1)) * TKN + d];
    g_t[idx] = v + pos[n * TKN + d];
}

// ---------------- fused scores + softmax ----------------
#define SC_STRIDE 264
#define SS_SMEM ((2*64*68 + 64*SC_STRIDE) * 4)   // 102400
__global__ void __launch_bounds__(256) attn_score_softmax_k(
    const unsigned* __restrict__ QK, float* __restrict__ P)
{
    extern __shared__ unsigned ssm[];
    unsigned* Qs = ssm;
    unsigned* Ks = ssm + 64 * 68;
    float*    Sc = (float*)(ssm + 2 * 64 * 68);

    int bh = blockIdx.y, b = bh / HH, h = bh % HH;
    int q0 = blockIdx.x * 64;
    const unsigned* Qb = QK + (size_t)b * NP1 * QKW + h * ZZ;
    const unsigned* Kb = Qb + TKN;
    int tid = threadIdx.x;
    int lane = tid & 31, wid = tid >> 5;
    int wm = (wid & 3) * 16, wn = (wid >> 2) * 32;
    int g = lane >> 2, tig = lane & 3;

#pragma unroll
    for (int s = 0; s < 4; s++) {
        int id = tid + s * 256;
        int r = id >> 4, c4 = (id & 15) << 2;
        uint4 qv = (q0 + r < NP1) ? *(const uint4*)(Qb + (size_t)(q0 + r) * QKW + c4)
                                  : make_uint4(0u, 0u, 0u, 0u);
        *(uint4*)&Qs[r * 68 + c4] = qv;
    }

    for (int kt = 0; kt < 4; kt++) {
        int k0 = kt * 64;
        __syncthreads();
#pragma unroll
        for (int s = 0; s < 4; s++) {
            int id = tid + s * 256;
            int r = id >> 4, c4 = (id & 15) << 2;
            uint4 kv = (k0 + r < NP1) ? *(const uint4*)(Kb + (size_t)(k0 + r) * QKW + c4)
                                      : make_uint4(0u, 0u, 0u, 0u);
            *(uint4*)&Ks[r * 68 + c4] = kv;
        }
        __syncthreads();

        float acc[4][4];
#pragma unroll
        for (int ni = 0; ni < 4; ni++)
#pragma unroll
            for (int v = 0; v < 4; v++) acc[ni][v] = 0.f;
#pragma unroll
        for (int ks = 0; ks < 8; ks++) {
            unsigned af[4], bf[4][2];
            const unsigned* pa = Qs + (wm + g) * 68 + ks * 8 + tig;
            af[0] = pa[0]; af[1] = pa[8 * 68]; af[2] = pa[4]; af[3] = pa[8 * 68 + 4];
#pragma unroll
            for (int ni = 0; ni < 4; ni++) {
                const unsigned* pb = Ks + (wn + ni * 8 + g) * 68 + ks * 8 + tig;
                bf[ni][0] = pb[0]; bf[ni][1] = pb[4];
            }
#pragma unroll
            for (int ni = 0; ni < 4; ni++)
                mma8(acc[ni], af, bf[ni]);
        }
#pragma unroll
        for (int half = 0; half < 2; half++) {
            int row = wm + g + half * 8;
#pragma unroll
            for (int ni = 0; ni < 4; ni++) {
                int col = k0 + wn + ni * 8 + tig * 2;
                Sc[row * SC_STRIDE + col]     = acc[ni][half * 2 + 0];
                Sc[row * SC_STRIDE + col + 1] = acc[ni][half * 2 + 1];
            }
        }
    }
    __syncthreads();

    float* Pp = P + (size_t)bh * NP1 * NP1;
#pragma unroll
    for (int rr = 0; rr < 8; rr++) {
        int row = wid * 8 + rr;
        int grow = q0 + row;
        if (grow >= NP1) continue;
        float vals[7];
        float m = -1e30f;
#pragma unroll
        for (int i = 0; i < 7; i++) {
            int c = lane + i * 32;
            float v = (c < NP1) ? BETA_S * Sc[row * SC_STRIDE + c] : -1e30f;
            vals[i] = v;
            m = fmaxf(m, v);
        }
#pragma unroll
        for (int o = 16; o; o >>= 1) m = fmaxf(m, __shfl_xor_sync(0xffffffffu, m, o));
        float s = 0.f;
#pragma unroll
        for (int i = 0; i < 7; i++) {
            int c = lane + i * 32;
            float e = (c < NP1) ? expf(vals[i] - m) : 0.f;
            vals[i] = e; s += e;
        }
#pragma unroll
        for (int o = 16; o; o >>= 1) s += __shfl_xor_sync(0xffffffffu, s, o);
        float inv = 1.f / s;
        float* prow = Pp + (size_t)grow * NP1;
#pragma unroll
        for (int i = 0; i < 7; i++) {
            int c = lane + i * 32;
            if (c < NP1) prow[c] = __uint_as_float(f2tf(vals[i] * inv));
        }
    }
}

// ---------------- attention PV via mma ----------------
template<bool TRANSP>
__global__ void __launch_bounds__(128) attn_av_mma_k(
    const float* __restrict__ Pb, const unsigned* __restrict__ QK,
    unsigned* __restrict__ OutB, int v_off, int o_off)
{
    __shared__ unsigned Ps[64 * 36];
    __shared__ unsigned Vs[32 * 72];
    int bh = blockIdx.y, b = bh / HH, h = bh % HH;
    const float* Pp = Pb + (size_t)bh * NP1 * NP1;
    const unsigned* Vb = QK + (size_t)b * NP1 * QKW + v_off + h * ZZ;
    unsigned* Ob = OutB + (size_t)b * NP1 * BIGK + o_off + h * ZZ;
    int m0 = blockIdx.x * 64;
    int tid = threadIdx.x, lane = tid & 31, wid = tid >> 5;
    int g = lane >> 2, tig = lane & 3, wm = wid * 16;
    float acc[8][4];
#pragma unroll
    for (int ni = 0; ni < 8; ni++)
#pragma unroll
        for (int v = 0; v < 4; v++) acc[ni][v] = 0.f;

    for (int kb = 0; kb < NP1; kb += 32) {
        __syncthreads();
#pragma unroll
        for (int s = 0; s < 16; s++) {
            int id = tid + s * 128;
            int r, kk;
            if (!TRANSP) { r = id >> 5; kk = id & 31; }
            else         { r = id & 63; kk = id >> 6; }
            float v = 0.f;
            int mg = m0 + r, kg = kb + kk;
            if (mg < NP1 && kg < NP1)
                v = TRANSP ? Pp[(size_t)kg * NP1 + mg] : Pp[(size_t)mg * NP1 + kg];
            Ps[r * 36 + kk] = __float_as_uint(v);
        }
#pragma unroll
        for (int s = 0; s < 4; s++) {
            int id = tid + s * 128;
            int r = id >> 4, c4 = (id & 15) << 2;
            uint4 v = (kb + r < NP1) ? *(const uint4*)(Vb + (size_t)(kb + r) * QKW + c4)
                                     : make_uint4(0u, 0u, 0u, 0u);
            *(uint4*)&Vs[r * 72 + c4] = v;
        }
        __syncthreads();
#pragma unroll
        for (int ks = 0; ks < 4; ks++) {
            unsigned af[4], bf[8][2];
            const unsigned* pa = Ps + (wm + g) * 36 + ks * 8 + tig;
            af[0] = pa[0]; af[1] = pa[8 * 36]; af[2] = pa[4]; af[3] = pa[8 * 36 + 4];
#pragma unroll
            for (int ni = 0; ni < 8; ni++) {
                const unsigned* pb = Vs + (ks * 8 + tig) * 72 + ni * 8 + g;
                bf[ni][0] = pb[0]; bf[ni][1] = pb[4 * 72];
            }
#pragma unroll
            for (int ni = 0; ni < 8; ni++)
                mma8(acc[ni], af, bf[ni]);
        }
    }
#pragma unroll
    for (int half = 0; half < 2; half++) {
        int row = m0 + wm + g + half * 8;
        if (row < NP1) {
            unsigned* orow = Ob + (size_t)row * BIGK;
#pragma unroll
            for (int ni = 0; ni < 8; ni++) {
                int col = ni * 8 + tig * 2;
                orow[col]     = f2tf(acc[ni][half * 2]);
                orow[col + 1] = f2tf(acc[ni][half * 2 + 1]);
            }
        }
    }
}

// ---------------- final copy (drop cls row) ----------------
__global__ void copy_out_k(const float* __restrict__ Y, float* __restrict__ out)
{
    int idx = blockIdx.x * 256 + threadIdx.x;
    if (idx >= BB * NTOK * TKN) return;
    int d = idx % TKN;
    int r = idx / TKN;
    int b = r / NTOK, j = r % NTOK;
    out[idx] = Y[((size_t)(b * NP1 + j + 1)) * TKN + d];
}

// ---------------- driver ----------------
extern "C" void kernel_launch(void* const* d_in, const int* in_sizes, int n_in,
                              void* d_out, int out_size)
{
    const float* x      = (const float*)d_in[0];
    const float* w_enc  = (const float*)d_in[1];
    const float* b_enc  = (const float*)d_in[2];
    const float* cls    = (const float*)d_in[3];
    const float* pos    = (const float*)d_in[4];
    const float* eln_g  = (const float*)d_in[5];
    const float* eln_b  = (const float*)d_in[6];
    const float* wq     = (const float*)d_in[7];
    const float* wk     = (const float*)d_in[8];
    const float* w_hop  = (const float*)d_in[9];
    const float* dec_w  = (const float*)d_in[10];
    const float* dec_b  = (const float*)d_in[11];
    const float* w_dec  = (const float*)d_in[12];
    const float* b_dec  = (const float*)d_in[13];
    float* out = (float*)d_out;

    float *t_, *P_, *tmp_;
    unsigned *g_, *qk_, *dqdkh_, *wstack_, *enct_, *dect_, *xt_;
    cudaGetSymbolAddress((void**)&t_,     g_t);
    cudaGetSymbolAddress((void**)&g_,     g_g);
    cudaGetSymbolAddress((void**)&qk_,    g_qk);
    cudaGetSymbolAddress((void**)&dqdkh_, g_dqdkh);
    cudaGetSymbolAddress((void**)&P_,     g_P);
    cudaGetSymbolAddress((void**)&tmp_,   g_tmp);
    cudaGetSymbolAddress((void**)&wstack_,g_wstack);
    cudaGetSymbolAddress((void**)&enct_,  g_enct);
    cudaGetSymbolAddress((void**)&dect_,  g_dect);
    cudaGetSymbolAddress((void**)&xt_,    g_xt);

    cudaFuncSetAttribute((const void*)mma_gemm_k<false, true,  false, false, false>,
                         cudaFuncAttributeMaxDynamicSharedMemorySize, SMEM_GEMM_BYTES);
    cudaFuncSetAttribute((const void*)mma_gemm_k<false, false, false, false, true>,
                         cudaFuncAttributeMaxDynamicSharedMemorySize, SMEM_GEMM_BYTES);
    cudaFuncSetAttribute((const void*)mma_gemm_k<false, false, true,  false, true>,
                         cudaFuncAttributeMaxDynamicSharedMemorySize, SMEM_GEMM_BYTES);
    cudaFuncSetAttribute((const void*)mma_gemm_k<true,  false, false, true,  false>,
                         cudaFuncAttributeMaxDynamicSharedMemorySize, SMEM_GEMM_BYTES);
    cudaFuncSetAttribute((const void*)attn_score_softmax_k,
                         cudaFuncAttributeMaxDynamicSharedMemorySize, SS_SMEM);

    const dim3 blk256(256);
    const dim3 blk(256);
    const int  mtiles = (MROWS + BM - 1) / BM;   // 25
    const dim3 gridProj(QKW / BN, mtiles);       // (12, 25)
    const dim3 gridHid(HIDN / BN, mtiles);       // (24, 25)
    const dim3 gridMega(TKN / BN, mtiles);       // (6, 25)
    const dim3 gridEnc(TKN / BN, (MENC + BM - 1) / BM);

    // one-time tf32 conversions (wstack = [wq | wk | w_hop])
    cvt_tf32_k<<<(TKN*TKN + 255) / 256, blk>>>(wq,    wstack_,              TKN*TKN);
    cvt_tf32_k<<<(TKN*TKN + 255) / 256, blk>>>(wk,    wstack_ + TKN*TKN,    TKN*TKN);
    cvt_tf32_k<<<(HIDN*TKN + 255) / 256, blk>>>(w_hop, wstack_ + 2*TKN*TKN, HIDN*TKN);
    cvt_tf32_k<<<(TKN*TKN + 255) / 256, blk>>>(w_enc, enct_, TKN*TKN);
    cvt_tf32_k<<<(TKN*TKN + 255) / 256, blk>>>(w_dec, dect_, TKN*TKN);
    cvt_tf32_k<<<(MENC*TKN + 255) / 256, blk>>>(x,     xt_,   MENC*TKN);

    // encode + assemble
    mma_gemm_k<false, true, false, false, false><<<gridEnc, blk256, SMEM_GEMM_BYTES>>>(
        xt_, enct_, b_enc, tmp_, MENC, TKN, TKN, TKN);
    assemble_t_k<<<(MROWS * TKN + 255) / 256, blk>>>(tmp_, cls, pos);

    for (int s = 0; s < KSTEPS; s++) {
        ln_kernel<<<MROWS, blk>>>(t_, eln_g, eln_b, g_, 1);
        mma_gemm_k<false, false, false, false, true><<<gridProj, blk256, SMEM_GEMM_BYTES>>>(
            g_, wstack_, nullptr, (float*)qk_, MROWS, QKW, TKN, QKW);
        attn_score_softmax_k<<<dim3(4, BHN), blk, SS_SMEM>>>(qk_, P_);
        attn_av_mma_k<false><<<dim3(4, BHN), dim3(128)>>>(P_, qk_, dqdkh_, TKN, 0);
        attn_av_mma_k<true ><<<dim3(4, BHN), dim3(128)>>>(P_, qk_, dqdkh_, 0, TKN);
        mma_gemm_k<false, false, true, false, true><<<gridHid, blk256, SMEM_GEMM_BYTES>>>(
            g_, wstack_ + 2*TKN*TKN, nullptr, (float*)(dqdkh_ + QKW), MROWS, HIDN, TKN, BIGK);
        mma_gemm_k<true, false, false, true, false><<<gridMega, blk256, SMEM_GEMM_BYTES>>>(
            dqdkh_, wstack_, nullptr, t_, MROWS, TKN, BIGK, TKN);
    }

    ln_kernel<<<MROWS, blk>>>(t_, dec_w, dec_b, g_, 0);
    mma_gemm_k<false, true, false, false, false><<<gridMega, blk256, SMEM_GEMM_BYTES>>>(
        g_, dect_, b_dec, tmp_, MROWS, TKN, TKN, TKN);
    copy_out_k<<<(BB * NTOK * TKN + 255) / 256, blk>>>(tmp_, out);
}

// round 9
// speedup vs baseline: 4.9862x; 1.4324x over previous
#include <cuda_runtime.h>
#include <cuda_fp16.h>
#include <math.h>

// ---------------- problem constants ----------------
#define BB    32
#define NTOK  196
#define NP1   197
#define TKN   768
#define HH    12
#define ZZ    64
#define HIDN  3072
#define MROWS (BB*NP1)    // 6304
#define MENC  (BB*NTOK)   // 6272
#define BHN   (BB*HH)     // 384
#define KSTEPS 12
#define BETA_S 0.125f
#define EPS_LN 1e-5f
#define QKW   1536
#define BIGK  4608

typedef unsigned short ushort_t;

// ---------------- scratch (device globals; no allocation) ----------------
__device__ float    g_t    [MROWS*TKN];      // fp32 state
__device__ ushort_t g_g    [MROWS*TKN];      // fp16
__device__ ushort_t g_qk   [MROWS*QKW];      // fp16: q | k
__device__ ushort_t g_dqdkh[MROWS*BIGK];     // fp16: dq | dk | relu(h)
__device__ ushort_t g_P    [BHN*NP1*NP1];    // fp16 post-softmax
__device__ float    g_tmp  [MROWS*TKN];      // fp32 temp
__device__ ushort_t g_wstack [BIGK*TKN];     // fp16: [wq;wk;whop] rows
__device__ ushort_t g_wstackT[TKN*BIGK];     // fp16: transpose of wstack
__device__ ushort_t g_enct [TKN*TKN];
__device__ ushort_t g_dect [TKN*TKN];
__device__ ushort_t g_xt   [MENC*TKN];

__device__ __forceinline__ ushort_t f2h(float f) {
    return __half_as_ushort(__float2half_rn(f));
}

__device__ __forceinline__ void mma16(float c[4], const unsigned a[4], const unsigned b[2]) {
    asm volatile(
        "mma.sync.aligned.m16n8k16.row.col.f32.f16.f16.f32 "
        "{%0,%1,%2,%3}, {%4,%5,%6,%7}, {%8,%9}, {%0,%1,%2,%3};\n"
        : "+f"(c[0]), "+f"(c[1]), "+f"(c[2]), "+f"(c[3])
        : "r"(a[0]), "r"(a[1]), "r"(a[2]), "r"(a[3]), "r"(b[0]), "r"(b[1]));
}

__global__ void cvt_h_k(const float* __restrict__ in, ushort_t* __restrict__ out, int n)
{
    int i = blockIdx.x * 256 + threadIdx.x;
    if (i < n) out[i] = f2h(in[i]);
}

// tiled half transpose: out[Cc x R] = in[R x Cc]^T
__global__ void trans_h_k(const ushort_t* __restrict__ in, ushort_t* __restrict__ out,
                          int R, int Cc)
{
    __shared__ ushort_t tile[32][33];
    int c0 = blockIdx.x * 32, r0 = blockIdx.y * 32;
    int x = threadIdx.x, y = threadIdx.y;
#pragma unroll
    for (int j = 0; j < 32; j += 8) {
        int r = r0 + y + j, c = c0 + x;
        tile[y + j][x] = (r < R && c < Cc) ? in[(size_t)r * Cc + c] : (ushort_t)0;
    }
    __syncthreads();
#pragma unroll
    for (int j = 0; j < 32; j += 8) {
        int r = c0 + y + j, c = r0 + x;
        if (r < Cc && c < R) out[(size_t)r * R + c] = tile[x][y + j];
    }
}

// ============ fp16 GEMM (NT): BM=256 BN=128 BK=64, 256 thr, warp 64x64 ============
#define STAGES 3
#define BM 256
#define BN 128
#define BKH 64
#define AS_H 72                     // halfs per row (stride); 36 words
#define A_STG_H (BM*AS_H)           // 18432 halfs
#define B_STG_H (128*AS_H)          // 9216 halfs
#define SMEM_GEMM_BYTES (STAGES*(A_STG_H+B_STG_H)*2)   // 165888

__device__ __forceinline__ void cp16(unsigned dst, const void* src, int sz) {
    asm volatile("cp.async.cg.shared.global [%0], [%1], 16, %2;\n"
                 :: "r"(dst), "l"(src), "r"(sz));
}
__device__ __forceinline__ void cp_commit() { asm volatile("cp.async.commit_group;\n"); }
__device__ __forceinline__ void cp_wait1()  { asm volatile("cp.async.wait_group 1;\n"); }

__device__ __forceinline__ void load_stage_h(
    const ushort_t* __restrict__ A, const ushort_t* __restrict__ B,
    int M, int K, int m0, int n0, int kt, int tid,
    unsigned sA, unsigned sB)
{
#pragma unroll
    for (int s = 0; s < 8; s++) {
        int id = tid + s * 256;
        int r = id >> 3, c8 = (id & 7) << 3;
        unsigned dst = sA + (unsigned)(r * AS_H + c8) * 2u;
        bool ok = (m0 + r < M);
        const ushort_t* src = ok ? (A + (size_t)(m0 + r) * K + kt + c8) : A;
        cp16(dst, src, ok ? 16 : 0);
    }
#pragma unroll
    for (int s = 0; s < 4; s++) {
        int id = tid + s * 256;
        int r = id >> 3, c8 = (id & 7) << 3;
        unsigned dst = sB + (unsigned)(r * AS_H + c8) * 2u;
        cp16(dst, B + (size_t)(n0 + r) * K + kt + c8, 16);
    }
}

template<bool BIAS, bool RELU, bool ACC, bool OTF>
__global__ void __launch_bounds__(256, 1) gemm_h_k(
    const ushort_t* __restrict__ A, const ushort_t* __restrict__ B,
    const float* __restrict__ bias, void* __restrict__ Cv,
    int M, int N, int K, int ldc)
{
    extern __shared__ ushort_t smh[];
    const int tid = threadIdx.x;
    const int m0 = blockIdx.y * BM, n0 = blockIdx.x * BN;
    const int lane = tid & 31, wid = tid >> 5;
    const int wm = (wid & 3) * 64, wn = (wid >> 2) * 64;
    const int g = lane >> 2, tig = lane & 3;

    unsigned smem_u = (unsigned)__cvta_generic_to_shared(smh);
    unsigned sB_base = smem_u + (unsigned)(STAGES * A_STG_H) * 2u;

    float acc[4][8][4];
#pragma unroll
    for (int mi = 0; mi < 4; mi++)
#pragma unroll
        for (int ni = 0; ni < 8; ni++)
#pragma unroll
            for (int v = 0; v < 4; v++) acc[mi][ni][v] = 0.f;

    const int niter = K >> 6;

#pragma unroll
    for (int p = 0; p < STAGES - 1; p++) {
        load_stage_h(A, B, M, K, m0, n0, p * BKH, tid,
                     smem_u + (unsigned)(p * A_STG_H) * 2u,
                     sB_base + (unsigned)(p * B_STG_H) * 2u);
        cp_commit();
    }

    int stc = 0;
    for (int it = 0; it < niter; it++) {
        cp_wait1();
        __syncthreads();

        int pf = it + STAGES - 1;
        if (pf < niter) {
            int st = pf % STAGES;
            load_stage_h(A, B, M, K, m0, n0, pf * BKH, tid,
                         smem_u + (unsigned)(st * A_STG_H) * 2u,
                         sB_base + (unsigned)(st * B_STG_H) * 2u);
        }
        cp_commit();

        const unsigned* Aw = (const unsigned*)(smh + stc * A_STG_H);
        const unsigned* Bw = (const unsigned*)(smh + STAGES * A_STG_H + stc * B_STG_H);
        stc = (stc + 1 == STAGES) ? 0 : stc + 1;
#pragma unroll
        for (int ks = 0; ks < 4; ks++) {
            unsigned af[4][4], bf[8][2];
#pragma unroll
            for (int mi = 0; mi < 4; mi++) {
                const unsigned* p0 = Aw + (wm + mi * 16 + g) * 36 + ks * 8 + tig;
                af[mi][0] = p0[0];
                af[mi][1] = p0[8 * 36];
                af[mi][2] = p0[4];
                af[mi][3] = p0[8 * 36 + 4];
            }
#pragma unroll
            for (int ni = 0; ni < 8; ni++) {
                const unsigned* p = Bw + (wn + ni * 8 + g) * 36 + ks * 8 + tig;
                bf[ni][0] = p[0];
                bf[ni][1] = p[4];
            }
#pragma unroll
            for (int mi = 0; mi < 4; mi++)
#pragma unroll
                for (int ni = 0; ni < 8; ni++)
                    mma16(acc[mi][ni], af[mi], bf[ni]);
        }
    }

#pragma unroll
    for (int mi = 0; mi < 4; mi++) {
#pragma unroll
        for (int half = 0; half < 2; half++) {
            int row = m0 + wm + mi * 16 + g + half * 8;
            if (row < M) {
#pragma unroll
                for (int ni = 0; ni < 8; ni++) {
                    int col = n0 + wn + ni * 8 + tig * 2;
                    float v0 = acc[mi][ni][half * 2 + 0];
                    float v1 = acc[mi][ni][half * 2 + 1];
                    if (BIAS) { v0 += bias[col]; v1 += bias[col + 1]; }
                    if (RELU) { v0 = fmaxf(v0, 0.f); v1 = fmaxf(v1, 0.f); }
                    if (OTF) {
                        ushort_t* crow = (ushort_t*)Cv + (size_t)row * ldc;
                        crow[col] = f2h(v0); crow[col + 1] = f2h(v1);
                    } else {
                        float* crow = (float*)Cv + (size_t)row * ldc;
                        if (ACC) { v0 += crow[col]; v1 += crow[col + 1]; }
                        crow[col] = v0; crow[col + 1] = v1;
                    }
                }
            }
        }
    }
}

// ---------------- LayerNorm (writes fp16) ----------------
__device__ __forceinline__ float block_sum_256(float v, float* red)
{
    int lane = threadIdx.x & 31, w = threadIdx.x >> 5;
#pragma unroll
    for (int o = 16; o; o >>= 1) v += __shfl_xor_sync(0xffffffffu, v, o);
    if (lane == 0) red[w] = v;
    __syncthreads();
    if (w == 0) {
        float r = (lane < 8) ? red[lane] : 0.f;
#pragma unroll
        for (int o = 4; o; o >>= 1) r += __shfl_xor_sync(0xffffffffu, r, o);
        if (lane == 0) red[0] = r;
    }
    __syncthreads();
    float out = red[0];
    __syncthreads();
    return out;
}

__global__ void __launch_bounds__(256) ln_kernel(
    const float* __restrict__ X, const float* __restrict__ w,
    const float* __restrict__ bvec, ushort_t* __restrict__ Y, int scalar_w)
{
    __shared__ float red[32];
    int row = blockIdx.x;
    const float* x = X + (size_t)row * TKN;
    ushort_t* y = Y + (size_t)row * TKN;
    int tid = threadIdx.x;
    float v[3];
    float s = 0.f, ss = 0.f;
#pragma unroll
    for (int i = 0; i < 3; i++) {
        float t = x[tid + i * 256];
        v[i] = t; s += t; ss += t * t;
    }
    float sum  = block_sum_256(s, red);
    float sum2 = block_sum_256(ss, red);
    float mu = sum * (1.f / TKN);
    float var = sum2 * (1.f / TKN) - mu * mu;
    float r = rsqrtf(var + EPS_LN);
#pragma unroll
    for (int i = 0; i < 3; i++) {
        int c = tid + i * 256;
        float gv = (v[i] - mu) * r;
        float wv = scalar_w ? w[0] : w[c];
        y[c] = f2h(gv * wv + bvec[c]);
    }
}

// ---------------- assemble t = [cls ; enc] + pos ----------------
__global__ void assemble_t_k(const float* __restrict__ enc,
                             const float* __restrict__ cls,
                             const float* __restrict__ pos)
{
    int idx = blockIdx.x * 256 + threadIdx.x;
    if (idx >= MROWS * TKN) return;
    int d = idx % TKN;
    int row = idx / TKN;
    int b = row / NP1, n = row % NP1;
    float v;
    if (n == 0) v = cls[d];
    else        v = enc[((size_t)(b * NTOK + n - 1)) * TKN + d];
    g_t[idx] = v + pos[n * TKN + d];
}

// ---------------- fused scores + softmax (fp16 in, fp16 P out) ----------------
// grid (4 qtiles, BHN), 256 threads.
// smem: Q 64x72 h + K 64x72 h + Sc 64x264 f32
#define SC_STRIDE 264
#define SS_SMEM (2*64*AS_H*2 + 64*SC_STRIDE*4)   // 18432 + 67584 = 86016
__global__ void __launch_bounds__(256) attn_score_softmax_k(
    const ushort_t* __restrict__ QK, ushort_t* __restrict__ P)
{
    extern __shared__ ushort_t ssm[];
    ushort_t* Qs = ssm;
    ushort_t* Ks = ssm + 64 * AS_H;
    float*    Sc = (float*)(ssm + 2 * 64 * AS_H);

    int bh = blockIdx.y, b = bh / HH, h = bh % HH;
    int q0 = blockIdx.x * 64;
    const ushort_t* Qb = QK + (size_t)b * NP1 * QKW + h * ZZ;
    const ushort_t* Kb = Qb + TKN;
    int tid = threadIdx.x;
    int lane = tid & 31, wid = tid >> 5;
    int wm = (wid & 3) * 16, wn = (wid >> 2) * 32;
    int g = lane >> 2, tig = lane & 3;

    // load Q tile: 64 rows x 64 halfs = 512 uint4 chunks (2 per thread)
#pragma unroll
    for (int s = 0; s < 2; s++) {
        int id = tid + s * 256;
        int r = id >> 3, c8 = (id & 7) << 3;
        uint4 qv = (q0 + r < NP1) ? *(const uint4*)(Qb + (size_t)(q0 + r) * QKW + c8)
                                  : make_uint4(0u, 0u, 0u, 0u);
        *(uint4*)&Qs[r * AS_H + c8] = qv;
    }

    for (int kt = 0; kt < 4; kt++) {
        int k0 = kt * 64;
        __syncthreads();
#pragma unroll
        for (int s = 0; s < 2; s++) {
            int id = tid + s * 256;
            int r = id >> 3, c8 = (id & 7) << 3;
            uint4 kv = (k0 + r < NP1) ? *(const uint4*)(Kb + (size_t)(k0 + r) * QKW + c8)
                                      : make_uint4(0u, 0u, 0u, 0u);
            *(uint4*)&Ks[r * AS_H + c8] = kv;
        }
        __syncthreads();

        const unsigned* Qw = (const unsigned*)Qs;
        const unsigned* Kw = (const unsigned*)Ks;
        float acc[4][4];
#pragma unroll
        for (int ni = 0; ni < 4; ni++)
#pragma unroll
            for (int v = 0; v < 4; v++) acc[ni][v] = 0.f;
#pragma unroll
        for (int ks = 0; ks < 4; ks++) {
            unsigned af[4], bf[4][2];
            const unsigned* pa = Qw + (wm + g) * 36 + ks * 8 + tig;
            af[0] = pa[0]; af[1] = pa[8 * 36]; af[2] = pa[4]; af[3] = pa[8 * 36 + 4];
#pragma unroll
            for (int ni = 0; ni < 4; ni++) {
                const unsigned* pb = Kw + (wn + ni * 8 + g) * 36 + ks * 8 + tig;
                bf[ni][0] = pb[0]; bf[ni][1] = pb[4];
            }
#pragma unroll
            for (int ni = 0; ni < 4; ni++)
                mma16(acc[ni], af, bf[ni]);
        }
#pragma unroll
        for (int half = 0; half < 2; half++) {
            int row = wm + g + half * 8;
#pragma unroll
            for (int ni = 0; ni < 4; ni++) {
                int col = k0 + wn + ni * 8 + tig * 2;
                Sc[row * SC_STRIDE + col]     = acc[ni][half * 2 + 0];
                Sc[row * SC_STRIDE + col + 1] = acc[ni][half * 2 + 1];
            }
        }
    }
    __syncthreads();

    ushort_t* Pp = P + (size_t)bh * NP1 * NP1;
#pragma unroll
    for (int rr = 0; rr < 8; rr++) {
        int row = wid * 8 + rr;
        int grow = q0 + row;
        if (grow >= NP1) continue;
        float vals[7];
        float m = -1e30f;
#pragma unroll
        for (int i = 0; i < 7; i++) {
            int c = lane + i * 32;
            float v = (c < NP1) ? BETA_S * Sc[row * SC_STRIDE + c] : -1e30f;
            vals[i] = v;
            m = fmaxf(m, v);
        }
#pragma unroll
        for (int o = 16; o; o >>= 1) m = fmaxf(m, __shfl_xor_sync(0xffffffffu, m, o));
        float s = 0.f;
#pragma unroll
        for (int i = 0; i < 7; i++) {
            int c = lane + i * 32;
            float e = (c < NP1) ? expf(vals[i] - m) : 0.f;
            vals[i] = e; s += e;
        }
#pragma unroll
        for (int o = 16; o; o >>= 1) s += __shfl_xor_sync(0xffffffffu, s, o);
        float inv = 1.f / s;
        ushort_t* prow = Pp + (size_t)grow * NP1;
#pragma unroll
        for (int i = 0; i < 7; i++) {
            int c = lane + i * 32;
            if (c < NP1) prow[c] = f2h(vals[i] * inv);
        }
    }
}

// ---------------- attention PV via fp16 mma ----------------
// TRANSP=false: dq = P @ K ; TRANSP=true: dk = P^T @ Q.
template<bool TRANSP>
__global__ void __launch_bounds__(128) attn_av_mma_k(
    const ushort_t* __restrict__ Pb, const ushort_t* __restrict__ QK,
    ushort_t* __restrict__ OutB, int v_off, int o_off)
{
    __shared__ ushort_t Ps[64 * 40];
    __shared__ ushort_t Vt[64 * 40];   // V transposed: [z][k]
    int bh = blockIdx.y, b = bh / HH, h = bh % HH;
    const ushort_t* Pp = Pb + (size_t)bh * NP1 * NP1;
    const ushort_t* Vb = QK + (size_t)b * NP1 * QKW + v_off + h * ZZ;
    ushort_t* Ob = OutB + (size_t)b * NP1 * BIGK + o_off + h * ZZ;
    int m0 = blockIdx.x * 64;
    int tid = threadIdx.x, lane = tid & 31, wid = tid >> 5;
    int g = lane >> 2, tig = lane & 3, wm = wid * 16;
    float acc[8][4];
#pragma unroll
    for (int ni = 0; ni < 8; ni++)
#pragma unroll
        for (int v = 0; v < 4; v++) acc[ni][v] = 0.f;

    for (int kb = 0; kb < NP1; kb += 32) {
        __syncthreads();
        // stage P chunk [64 m][32 k] as fp16
#pragma unroll
        for (int s = 0; s < 16; s++) {
            int id = tid + s * 128;
            int r, kk;
            if (!TRANSP) { r = id >> 5; kk = id & 31; }
            else         { r = id & 63; kk = id >> 6; }
            ushort_t v = 0;
            int mg = m0 + r, kg = kb + kk;
            if (mg < NP1 && kg < NP1)
                v = TRANSP ? Pp[(size_t)kg * NP1 + mg] : Pp[(size_t)mg * NP1 + kg];
            Ps[r * 40 + kk] = v;
        }
        // stage V transposed: Vt[z][k] from V[kb+r][z]
#pragma unroll
        for (int s = 0; s < 2; s++) {
            int id = tid + s * 128;
            int r = id >> 3, c8 = (id & 7) << 3;
            uint4 v = (kb + r < NP1) ? *(const uint4*)(Vb + (size_t)(kb + r) * QKW + c8)
                                     : make_uint4(0u, 0u, 0u, 0u);
            ushort_t hv[8];
            *(uint4*)hv = v;
#pragma unroll
            for (int j = 0; j < 8; j++) Vt[(c8 + j) * 40 + r] = hv[j];
        }
        __syncthreads();
        const unsigned* Pw = (const unsigned*)Ps;
        const unsigned* Vw = (const unsigned*)Vt;
#pragma unroll
        for (int ks = 0; ks < 2; ks++) {
            unsigned af[4], bf[8][2];
            const unsigned* pa = Pw + (wm + g) * 20 + ks * 8 + tig;
            af[0] = pa[0]; af[1] = pa[8 * 20]; af[2] = pa[4]; af[3] = pa[8 * 20 + 4];
#pragma unroll
            for (int ni = 0; ni < 8; ni++) {
                const unsigned* pb = Vw + (ni * 8 + g) * 20 + ks * 8 + tig;
                bf[ni][0] = pb[0]; bf[ni][1] = pb[4];
            }
#pragma unroll
            for (int ni = 0; ni < 8; ni++)
                mma16(acc[ni], af, bf[ni]);
        }
    }
#pragma unroll
    for (int half = 0; half < 2; half++) {
        int row = m0 + wm + g + half * 8;
        if (row < NP1) {
            ushort_t* orow = Ob + (size_t)row * BIGK;
#pragma unroll
            for (int ni = 0; ni < 8; ni++) {
                int col = ni * 8 + tig * 2;
                orow[col]     = f2h(acc[ni][half * 2]);
                orow[col + 1] = f2h(acc[ni][half * 2 + 1]);
            }
        }
    }
}

// ---------------- final copy (drop cls row) ----------------
__global__ void copy_out_k(const float* __restrict__ Y, float* __restrict__ out)
{
    int idx = blockIdx.x * 256 + threadIdx.x;
    if (idx >= BB * NTOK * TKN) return;
    int d = idx % TKN;
    int r = idx / TKN;
    int b = r / NTOK, j = r % NTOK;
    out[idx] = Y[((size_t)(b * NP1 + j + 1)) * TKN + d];
}

// ---------------- driver ----------------
extern "C" void kernel_launch(void* const* d_in, const int* in_sizes, int n_in,
                              void* d_out, int out_size)
{
    const float* x      = (const float*)d_in[0];
    const float* w_enc  = (const float*)d_in[1];
    const float* b_enc  = (const float*)d_in[2];
    const float* cls    = (const float*)d_in[3];
    const float* pos    = (const float*)d_in[4];
    const float* eln_g  = (const float*)d_in[5];
    const float* eln_b  = (const float*)d_in[6];
    const float* wq     = (const float*)d_in[7];
    const float* wk     = (const float*)d_in[8];
    const float* w_hop  = (const float*)d_in[9];
    const float* dec_w  = (const float*)d_in[10];
    const float* dec_b  = (const float*)d_in[11];
    const float* w_dec  = (const float*)d_in[12];
    const float* b_dec  = (const float*)d_in[13];
    float* out = (float*)d_out;

    float *t_, *tmp_;
    ushort_t *g_, *qk_, *dqdkh_, *P_, *wstack_, *wstackT_, *enct_, *dect_, *xt_;
    cudaGetSymbolAddress((void**)&t_,      g_t);
    cudaGetSymbolAddress((void**)&g_,      g_g);
    cudaGetSymbolAddress((void**)&qk_,     g_qk);
    cudaGetSymbolAddress((void**)&dqdkh_,  g_dqdkh);
    cudaGetSymbolAddress((void**)&P_,      g_P);
    cudaGetSymbolAddress((void**)&tmp_,    g_tmp);
    cudaGetSymbolAddress((void**)&wstack_, g_wstack);
    cudaGetSymbolAddress((void**)&wstackT_,g_wstackT);
    cudaGetSymbolAddress((void**)&enct_,   g_enct);
    cudaGetSymbolAddress((void**)&dect_,   g_dect);
    cudaGetSymbolAddress((void**)&xt_,     g_xt);

    cudaFuncSetAttribute((const void*)gemm_h_k<true,  false, false, false>,
                         cudaFuncAttributeMaxDynamicSharedMemorySize, SMEM_GEMM_BYTES);
    cudaFuncSetAttribute((const void*)gemm_h_k<false, false, false, true>,
                         cudaFuncAttributeMaxDynamicSharedMemorySize, SMEM_GEMM_BYTES);
    cudaFuncSetAttribute((const void*)gemm_h_k<false, true,  false, true>,
                         cudaFuncAttributeMaxDynamicSharedMemorySize, SMEM_GEMM_BYTES);
    cudaFuncSetAttribute((const void*)gemm_h_k<false, false, true,  false>,
                         cudaFuncAttributeMaxDynamicSharedMemorySize, SMEM_GEMM_BYTES);
    cudaFuncSetAttribute((const void*)attn_score_softmax_k,
                         cudaFuncAttributeMaxDynamicSharedMemorySize, SS_SMEM);

    const dim3 blk(256);
    const int  mtiles = (MROWS + BM - 1) / BM;   // 25
    const dim3 gridProj(QKW / BN, mtiles);       // (12, 25)
    const dim3 gridHid(HIDN / BN, mtiles);       // (24, 25)
    const dim3 gridMega(TKN / BN, mtiles);       // (6, 25)
    const dim3 gridEnc(TKN / BN, (MENC + BM - 1) / BM);

    // one-time fp16 conversions
    cvt_h_k<<<(TKN*TKN + 255) / 256, blk>>>(wq,    wstack_,              TKN*TKN);
    cvt_h_k<<<(TKN*TKN + 255) / 256, blk>>>(wk,    wstack_ + TKN*TKN,    TKN*TKN);
    cvt_h_k<<<(HIDN*TKN + 255) / 256, blk>>>(w_hop, wstack_ + 2*TKN*TKN, HIDN*TKN);
    cvt_h_k<<<(TKN*TKN + 255) / 256, blk>>>(w_enc, enct_, TKN*TKN);
    cvt_h_k<<<(TKN*TKN + 255) / 256, blk>>>(w_dec, dect_, TKN*TKN);
    cvt_h_k<<<(MENC*TKN + 255) / 256, blk>>>(x,     xt_,   MENC*TKN);
    trans_h_k<<<dim3((TKN + 31) / 32, (BIGK + 31) / 32), dim3(32, 8)>>>(
        wstack_, wstackT_, BIGK, TKN);

    // encode + assemble
    gemm_h_k<true, false, false, false><<<gridEnc, blk, SMEM_GEMM_BYTES>>>(
        xt_, enct_, b_enc, tmp_, MENC, TKN, TKN, TKN);
    assemble_t_k<<<(MROWS * TKN + 255) / 256, blk>>>(tmp_, cls, pos);

    for (int s = 0; s < KSTEPS; s++) {
        ln_kernel<<<MROWS, blk>>>(t_, eln_g, eln_b, g_, 1);
        // fused q|k projection (fp16 out)
        gemm_h_k<false, false, false, true><<<gridProj, blk, SMEM_GEMM_BYTES>>>(
            g_, wstack_, nullptr, qk_, MROWS, QKW, TKN, QKW);
        attn_score_softmax_k<<<dim3(4, BHN), blk, SS_SMEM>>>(qk_, P_);
        attn_av_mma_k<false><<<dim3(4, BHN), dim3(128)>>>(P_, qk_, dqdkh_, TKN, 0);
        attn_av_mma_k<true ><<<dim3(4, BHN), dim3(128)>>>(P_, qk_, dqdkh_, 0, TKN);
        // hopfield: relu(g @ w_hop^T) -> dqdkh cols 1536..4607 (fp16)
        gemm_h_k<false, true, false, true><<<gridHid, blk, SMEM_GEMM_BYTES>>>(
            g_, wstack_ + 2*TKN*TKN, nullptr, dqdkh_ + QKW, MROWS, HIDN, TKN, BIGK);
        // mega accumulate: t += [dq|dk|relu(h)] @ wstackT^T  (NT via pre-transposed weights)
        gemm_h_k<false, false, true, false><<<gridMega, blk, SMEM_GEMM_BYTES>>>(
            dqdkh_, wstackT_, nullptr, t_, MROWS, TKN, BIGK, TKN);
    }

    ln_kernel<<<MROWS, blk>>>(t_, dec_w, dec_b, g_, 0);
    gemm_h_k<true, false, false, false><<<gridMega, blk, SMEM_GEMM_BYTES>>>(
        g_, dect_, b_dec, tmp_, MROWS, TKN, TKN, TKN);
    copy_out_k<<<(BB * NTOK * TKN + 255) / 256, blk>>>(tmp_, out);
}